// round 2
// baseline (speedup 1.0000x reference)
#include <cuda_runtime.h>
#include <cuda_bf16.h>
#include <math.h>

#define B_ 8
#define SEQ 1124
#define EMB 1024
#define NH 16
#define HD 64
#define MLP 4096
#define M_ROWS (B_ * SEQ)          // 8992
#define NUM_Q 100
#define NUM_P 1024

// ---------------- scratch (device globals; no allocation allowed) ----------------
__device__ float g_xn[(size_t)M_ROWS * EMB];      // LN output (reused for LN1 and LN2)
__device__ float g_qkv[(size_t)M_ROWS * 3 * EMB]; // QKV projection
__device__ float g_attn[(size_t)M_ROWS * EMB];    // attention output (B,S,E)
__device__ float g_x1[(size_t)M_ROWS * EMB];      // x + attn proj (first residual)
__device__ float g_h[(size_t)M_ROWS * MLP];       // MLP hidden

// ---------------- LayerNorm ----------------
__global__ void __launch_bounds__(256) ln_kernel(const float* __restrict__ x,
                                                 const float* __restrict__ g,
                                                 const float* __restrict__ b,
                                                 float* __restrict__ out) {
    int row = blockIdx.x;
    const float* xr = x + (size_t)row * EMB;
    int t = threadIdx.x;
    float v[4];
    float s = 0.f, s2 = 0.f;
#pragma unroll
    for (int i = 0; i < 4; i++) {
        float val = xr[t + i * 256];
        v[i] = val;
        s += val;
        s2 += val * val;
    }
#pragma unroll
    for (int o = 16; o > 0; o >>= 1) {
        s += __shfl_xor_sync(0xffffffffu, s, o);
        s2 += __shfl_xor_sync(0xffffffffu, s2, o);
    }
    __shared__ float red[2][8];
    int w = t >> 5, lane = t & 31;
    if (lane == 0) { red[0][w] = s; red[1][w] = s2; }
    __syncthreads();
    float ts = 0.f, ts2 = 0.f;
#pragma unroll
    for (int i = 0; i < 8; i++) { ts += red[0][i]; ts2 += red[1][i]; }
    float mean = ts * (1.0f / EMB);
    float var = ts2 * (1.0f / EMB) - mean * mean;
    float inv = rsqrtf(var + 1e-6f);
    float* orow = out + (size_t)row * EMB;
#pragma unroll
    for (int i = 0; i < 4; i++) {
        int c = t + i * 256;
        orow[c] = (v[i] - mean) * inv * g[c] + b[c];
    }
}

// ---------------- tiled SGEMM with fused epilogue ----------------
// C[M,N] = A[M,K] @ B[K,N] (+bias) (gelu?) (+resid)
#define BM 128
#define BN 128
#define BK 16
__global__ void __launch_bounds__(256) sgemm_kernel(const float* __restrict__ A,
                                                    const float* __restrict__ Bm,
                                                    float* __restrict__ C,
                                                    int M, int N, int K,
                                                    const float* __restrict__ bias,
                                                    const float* __restrict__ resid,
                                                    int do_gelu) {
    __shared__ float As[BK][BM];
    __shared__ float Bs[BK][BN];
    int bm = blockIdx.y, bn = blockIdx.x;
    int tid = threadIdx.x;
    int tr = tid >> 4;        // 0..15
    int tc = tid & 15;        // 0..15
    int row0 = bm * BM, col0 = bn * BN;

    float acc[8][8];
#pragma unroll
    for (int i = 0; i < 8; i++)
#pragma unroll
        for (int j = 0; j < 8; j++) acc[i][j] = 0.f;

    for (int k0 = 0; k0 < K; k0 += BK) {
        // load A tile (128 x 16), transpose into As[k][m]
#pragma unroll
        for (int l = 0; l < 2; l++) {
            int idx = tid + l * 256;   // 0..511
            int ar = idx >> 2;         // 0..127
            int ac = (idx & 3) * 4;    // 0,4,8,12
            int grow = row0 + ar;
            float4 av = make_float4(0.f, 0.f, 0.f, 0.f);
            if (grow < M) av = *(const float4*)(A + (size_t)grow * K + k0 + ac);
            As[ac + 0][ar] = av.x;
            As[ac + 1][ar] = av.y;
            As[ac + 2][ar] = av.z;
            As[ac + 3][ar] = av.w;
        }
        // load B tile (16 x 128)
#pragma unroll
        for (int l = 0; l < 2; l++) {
            int idx = tid + l * 256;
            int br = idx >> 5;         // 0..15
            int bc = (idx & 31) * 4;   // 0..124
            float4 bv = *(const float4*)(Bm + (size_t)(k0 + br) * N + col0 + bc);
            *(float4*)&Bs[br][bc] = bv;
        }
        __syncthreads();
#pragma unroll
        for (int kk = 0; kk < BK; kk++) {
            float a[8], b[8];
#pragma unroll
            for (int i = 0; i < 8; i++) a[i] = As[kk][tr * 8 + i];
#pragma unroll
            for (int j = 0; j < 8; j++) b[j] = Bs[kk][tc * 8 + j];
#pragma unroll
            for (int i = 0; i < 8; i++)
#pragma unroll
                for (int j = 0; j < 8; j++) acc[i][j] = fmaf(a[i], b[j], acc[i][j]);
        }
        __syncthreads();
    }

#pragma unroll
    for (int i = 0; i < 8; i++) {
        int grow = row0 + tr * 8 + i;
        if (grow >= M) continue;
#pragma unroll
        for (int j = 0; j < 8; j++) {
            int gcol = col0 + tc * 8 + j;
            float v = acc[i][j];
            if (bias) v += bias[gcol];
            if (do_gelu) v = 0.5f * v * (1.0f + erff(v * 0.70710678118f));
            if (resid) v += resid[(size_t)grow * N + gcol];
            C[(size_t)grow * N + gcol] = v;
        }
    }
}

// ---------------- flash attention with fused mask ----------------
// qkv: [B,S,3*EMB] with q at +0, k at +1024, v at +2048, per-head slice h*64.
// out: [B,S,EMB] at h*64.
// 64 q-rows per block, K/V processed in 32-row chunks (36 chunks over 1152).
#define KCH 32
#define NCHUNK ((SEQ + KCH - 1) / KCH)   // 36
__global__ void __launch_bounds__(256) attn_kernel(const float* __restrict__ qkv,
                                                   const float* __restrict__ mask,
                                                   float* __restrict__ out) {
    int qt = blockIdx.x;     // 0..17
    int h = blockIdx.y;      // 0..15
    int b = blockIdx.z;      // 0..7
    int q0 = qt * 64;
    int tid = threadIdx.x;

    __shared__ float Qs[64][65];    // 4160 floats
    __shared__ float Ks[KCH][65];   // 2080
    __shared__ float Vs[KCH][65];   // 2080
    __shared__ float Ps[64][KCH + 1]; // 64*33 = 2112
    // total 10432 floats = 40.75 KB

    // load Q tile (64 rows x 64 dims)
#pragma unroll
    for (int l = 0; l < 4; l++) {
        int idx = tid + l * 256;      // 0..1023
        int r = idx >> 4;             // 0..63
        int c4 = (idx & 15) * 4;      // 0..60
        int s = q0 + r;
        float4 qv = make_float4(0.f, 0.f, 0.f, 0.f);
        if (s < SEQ)
            qv = *(const float4*)(qkv + (size_t)(b * SEQ + s) * 3072 + h * 64 + c4);
        Qs[r][c4 + 0] = qv.x; Qs[r][c4 + 1] = qv.y;
        Qs[r][c4 + 2] = qv.z; Qs[r][c4 + 3] = qv.w;
    }

    int r = tid >> 2;            // q-row within tile, 0..63
    int q = tid & 3;             // quarter, 0..3
    int cs = q * 8;              // this thread's 8 score columns within chunk
    int co = q * 16;             // this thread's 16 output head-dims
    int qrow = q0 + r;
    bool isquery = (qrow >= NUM_P) && (qrow < SEQ);
    const float* mrow = mask + ((size_t)b * NUM_Q + (qrow - NUM_P)) * NUM_P;

    float O[16];
#pragma unroll
    for (int j = 0; j < 16; j++) O[j] = 0.f;
    float m_prev = -1e30f, lsum_tot = 0.f;

    for (int chunk = 0; chunk < NCHUNK; chunk++) {
        int c0 = chunk * KCH;
        __syncthreads();   // previous chunk's Ks/Vs consumers done
        // load K and V chunk (32 rows x 64 dims): 512 float4 loads
        {
            int idx = tid;                 // 0..255  (2 float4 per thread)
#pragma unroll
            for (int l = 0; l < 2; l++) {
                int e = idx + l * 256;     // 0..511
                int rr = e >> 4;           // 0..31
                int c4 = (e & 15) * 4;     // 0..60
                int s = c0 + rr;
                float4 kv = make_float4(0.f, 0.f, 0.f, 0.f);
                float4 vv = make_float4(0.f, 0.f, 0.f, 0.f);
                if (s < SEQ) {
                    const float* base = qkv + (size_t)(b * SEQ + s) * 3072 + h * 64 + c4;
                    kv = *(const float4*)(base + 1024);
                    vv = *(const float4*)(base + 2048);
                }
                Ks[rr][c4 + 0] = kv.x; Ks[rr][c4 + 1] = kv.y;
                Ks[rr][c4 + 2] = kv.z; Ks[rr][c4 + 3] = kv.w;
                Vs[rr][c4 + 0] = vv.x; Vs[rr][c4 + 1] = vv.y;
                Vs[rr][c4 + 2] = vv.z; Vs[rr][c4 + 3] = vv.w;
            }
        }
        __syncthreads();

        // S = Q K^T for this thread's 8 columns
        float sc[8];
#pragma unroll
        for (int j = 0; j < 8; j++) sc[j] = 0.f;
        for (int d = 0; d < 64; d++) {
            float qv = Qs[r][d];
#pragma unroll
            for (int j = 0; j < 8; j++) sc[j] = fmaf(qv, Ks[cs + j][d], sc[j]);
        }
        // scale + mask
#pragma unroll
        for (int j = 0; j < 8; j++) {
            int kcol = c0 + cs + j;
            float v = sc[j] * 0.125f;
            if (kcol >= SEQ) {
                v = -1e30f;
            } else if (isquery && kcol < NUM_P) {
                if (!(mrow[kcol] > 0.5f)) v = -1e9f;
            }
            sc[j] = v;
        }
        // row max across the 4 threads of this row (consecutive lanes)
        float mx = -1e30f;
#pragma unroll
        for (int j = 0; j < 8; j++) mx = fmaxf(mx, sc[j]);
        mx = fmaxf(mx, __shfl_xor_sync(0xffffffffu, mx, 1));
        mx = fmaxf(mx, __shfl_xor_sync(0xffffffffu, mx, 2));
        float m_new = fmaxf(m_prev, mx);
        float ls = 0.f;
#pragma unroll
        for (int j = 0; j < 8; j++) {
            float p = __expf(sc[j] - m_new);
            Ps[r][cs + j] = p;
            ls += p;
        }
        ls += __shfl_xor_sync(0xffffffffu, ls, 1);
        ls += __shfl_xor_sync(0xffffffffu, ls, 2);
        float alpha = __expf(m_prev - m_new);
        lsum_tot = lsum_tot * alpha + ls;
        m_prev = m_new;
#pragma unroll
        for (int j = 0; j < 16; j++) O[j] *= alpha;
        __syncwarp();   // Ps row written by 4 same-warp threads
        // O += P @ V  (this thread's 16 output dims = co..co+15)
        for (int c = 0; c < KCH; c++) {
            float p = Ps[r][c];
#pragma unroll
            for (int j = 0; j < 16; j++) O[j] = fmaf(p, Vs[c][co + j], O[j]);
        }
    }

    if (qrow < SEQ) {
        float invl = 1.0f / lsum_tot;
        float* orow = out + (size_t)(b * SEQ + qrow) * EMB + h * 64 + co;
#pragma unroll
        for (int j = 0; j < 16; j++) orow[j] = O[j] * invl;
    }
}

// ---------------- launch ----------------
extern "C" void kernel_launch(void* const* d_in, const int* in_sizes, int n_in,
                              void* d_out, int out_size) {
    const float* x      = (const float*)d_in[0];
    const float* mask   = (const float*)d_in[1];
    const float* qkv_w  = (const float*)d_in[2];
    const float* proj_w = (const float*)d_in[3];
    const float* proj_b = (const float*)d_in[4];
    const float* ln1_g  = (const float*)d_in[5];
    const float* ln1_b  = (const float*)d_in[6];
    const float* ln2_g  = (const float*)d_in[7];
    const float* ln2_b  = (const float*)d_in[8];
    const float* fc1_w  = (const float*)d_in[9];
    const float* fc1_b  = (const float*)d_in[10];
    const float* fc2_w  = (const float*)d_in[11];
    const float* fc2_b  = (const float*)d_in[12];
    float* out = (float*)d_out;

    void *p_xn, *p_qkv, *p_attn, *p_x1, *p_h;
    cudaGetSymbolAddress(&p_xn, g_xn);
    cudaGetSymbolAddress(&p_qkv, g_qkv);
    cudaGetSymbolAddress(&p_attn, g_attn);
    cudaGetSymbolAddress(&p_x1, g_x1);
    cudaGetSymbolAddress(&p_h, g_h);
    float* xn = (float*)p_xn;
    float* qkv = (float*)p_qkv;
    float* attn = (float*)p_attn;
    float* x1 = (float*)p_x1;
    float* hbuf = (float*)p_h;

    const int MG = (M_ROWS + BM - 1) / BM;  // 71

    // 1) LN1
    ln_kernel<<<M_ROWS, 256>>>(x, ln1_g, ln1_b, xn);
    // 2) QKV GEMM: [8992,1024] @ [1024,3072]
    sgemm_kernel<<<dim3(3 * EMB / BN, MG), 256>>>(xn, qkv_w, qkv, M_ROWS, 3 * EMB, EMB,
                                                  nullptr, nullptr, 0);
    // 3) attention
    attn_kernel<<<dim3(18, NH, B_), 256>>>(qkv, mask, attn);
    // 4) proj + bias + residual(x) -> x1
    sgemm_kernel<<<dim3(EMB / BN, MG), 256>>>(attn, proj_w, x1, M_ROWS, EMB, EMB,
                                              proj_b, x, 0);
    // 5) LN2
    ln_kernel<<<M_ROWS, 256>>>(x1, ln2_g, ln2_b, xn);
    // 6) fc1 + bias + gelu
    sgemm_kernel<<<dim3(MLP / BN, MG), 256>>>(xn, fc1_w, hbuf, M_ROWS, MLP, EMB,
                                              fc1_b, nullptr, 1);
    // 7) fc2 + bias + residual(x1) -> out
    sgemm_kernel<<<dim3(EMB / BN, MG), 256>>>(hbuf, fc2_w, out, M_ROWS, EMB, MLP,
                                              fc2_b, x1, 0);
}

// round 5
// speedup vs baseline: 1.3749x; 1.3749x over previous
#include <cuda_runtime.h>
#include <cuda_bf16.h>
#include <math.h>
#include <stdint.h>

#define B_ 8
#define SEQ 1124
#define EMB 1024
#define NH 16
#define HD 64
#define MLP 4096
#define M_ROWS (B_ * SEQ)          // 8992
#define NUM_Q 100
#define NUM_P 1024

// ---------------- scratch (device globals; no allocation allowed) ----------------
__device__ float g_xn[(size_t)M_ROWS * EMB];
__device__ float g_qkv[(size_t)M_ROWS * 3 * EMB];
__device__ float g_attn[(size_t)M_ROWS * EMB];
__device__ float g_x1[(size_t)M_ROWS * EMB];
__device__ float g_h[(size_t)M_ROWS * MLP];

// ---------------- helpers ----------------
__device__ __forceinline__ uint32_t smem_u32(const void* p) {
    uint32_t a;
    asm("{ .reg .u64 t; cvta.to.shared.u64 t, %1; cvt.u32.u64 %0, t; }" : "=r"(a) : "l"(p));
    return a;
}
__device__ __forceinline__ void ldsm4(uint32_t* r, uint32_t addr) {
    asm volatile("ldmatrix.sync.aligned.m8n8.x4.shared.b16 {%0,%1,%2,%3}, [%4];"
        : "=r"(r[0]), "=r"(r[1]), "=r"(r[2]), "=r"(r[3]) : "r"(addr));
}
__device__ __forceinline__ void mma_bf16(float* d, const uint32_t* a, const uint32_t* b) {
    asm volatile("mma.sync.aligned.m16n8k16.row.col.f32.bf16.bf16.f32 "
        "{%0,%1,%2,%3}, {%4,%5,%6,%7}, {%8,%9}, {%0,%1,%2,%3};"
        : "+f"(d[0]), "+f"(d[1]), "+f"(d[2]), "+f"(d[3])
        : "r"(a[0]), "r"(a[1]), "r"(a[2]), "r"(a[3]), "r"(b[0]), "r"(b[1]));
}

// ---------------- LayerNorm ----------------
__global__ void __launch_bounds__(256) ln_kernel(const float* __restrict__ x,
                                                 const float* __restrict__ g,
                                                 const float* __restrict__ b,
                                                 float* __restrict__ out) {
    int row = blockIdx.x;
    const float* xr = x + (size_t)row * EMB;
    int t = threadIdx.x;
    float v[4];
    float s = 0.f, s2 = 0.f;
#pragma unroll
    for (int i = 0; i < 4; i++) {
        float val = xr[t + i * 256];
        v[i] = val;
        s += val;
        s2 += val * val;
    }
#pragma unroll
    for (int o = 16; o > 0; o >>= 1) {
        s += __shfl_xor_sync(0xffffffffu, s, o);
        s2 += __shfl_xor_sync(0xffffffffu, s2, o);
    }
    __shared__ float red[2][8];
    int w = t >> 5, lane = t & 31;
    if (lane == 0) { red[0][w] = s; red[1][w] = s2; }
    __syncthreads();
    float ts = 0.f, ts2 = 0.f;
#pragma unroll
    for (int i = 0; i < 8; i++) { ts += red[0][i]; ts2 += red[1][i]; }
    float mean = ts * (1.0f / EMB);
    float var = ts2 * (1.0f / EMB) - mean * mean;
    float inv = rsqrtf(var + 1e-6f);
    float* orow = out + (size_t)row * EMB;
#pragma unroll
    for (int i = 0; i < 4; i++) {
        int c = t + i * 256;
        orow[c] = (v[i] - mean) * inv * g[c] + b[c];
    }
}

// ---------------- mma.sync bf16 (3x split) GEMM, tile 128x128x32 ----------------
// C[M,N] = A[M,K] @ B[K,N] (+bias) (gelu?) (+resid)
#define GBM 128
#define GBN 128
#define GBK 32
#define APITCH 40   // bf16 elems per smem row (80B, conflict-free ldmatrix)

__global__ void __launch_bounds__(256) gemm_mma_kernel(const float* __restrict__ A,
                                                       const float* __restrict__ Bm,
                                                       float* __restrict__ C,
                                                       int M, int N, int K,
                                                       const float* __restrict__ bias,
                                                       const float* __restrict__ resid,
                                                       int do_gelu) {
    __shared__ __nv_bfloat16 sAh[GBM][APITCH];
    __shared__ __nv_bfloat16 sAl[GBM][APITCH];
    __shared__ __nv_bfloat16 sBh[GBN][APITCH];   // [n][k]
    __shared__ __nv_bfloat16 sBl[GBN][APITCH];

    int tid = threadIdx.x;
    int lane = tid & 31, wid = tid >> 5;
    int warp_m = wid >> 2;          // 0..1  -> 64 rows
    int warp_n = wid & 3;           // 0..3  -> 32 cols
    int row0 = blockIdx.y * GBM;
    int col0 = blockIdx.x * GBN;

    // ldmatrix lane address components
    int laneRA = (lane & 7) + ((lane >> 3) & 1) * 8;
    int laneKA = ((lane >> 4) & 1) * 8;
    int laneRB = (lane & 7) + ((lane >> 4) & 1) * 8;
    int laneKB = ((lane >> 3) & 1) * 8;
    uint32_t aHiB = smem_u32(&sAh[0][0]);
    uint32_t aLoB = smem_u32(&sAl[0][0]);
    uint32_t bHiB = smem_u32(&sBh[0][0]);
    uint32_t bLoB = smem_u32(&sBl[0][0]);

    // global load indices
    int bn = tid >> 1;
    int bkh = (tid & 1) * 16;

    float acc[4][4][4];
#pragma unroll
    for (int i = 0; i < 4; i++)
#pragma unroll
        for (int j = 0; j < 4; j++)
#pragma unroll
            for (int r = 0; r < 4; r++) acc[i][j][r] = 0.f;

    float4 rA[4];
    float rB[16];

    // prefetch stage 0
    {
#pragma unroll
        for (int l = 0; l < 4; l++) {
            int e = tid + l * 256;
            int gm = row0 + (e >> 3);
            int kq = (e & 7) * 4;
            rA[l] = make_float4(0.f, 0.f, 0.f, 0.f);
            if (gm < M) rA[l] = *(const float4*)(A + (size_t)gm * K + kq);
        }
        const float* bp = Bm + (size_t)bkh * N + col0 + bn;
#pragma unroll
        for (int kk = 0; kk < 16; kk++) rB[kk] = bp[(size_t)kk * N];
    }

    int nstages = K / GBK;
    for (int s = 0; s < nstages; s++) {
        __syncthreads();
        // store regs -> smem with bf16 hi/lo split
#pragma unroll
        for (int l = 0; l < 4; l++) {
            int e = tid + l * 256;
            int r = e >> 3;
            int c4 = (e & 7) * 4;
            float xs[4] = {rA[l].x, rA[l].y, rA[l].z, rA[l].w};
            __nv_bfloat16 h[4], lo[4];
#pragma unroll
            for (int u = 0; u < 4; u++) {
                h[u] = __float2bfloat16_rn(xs[u]);
                lo[u] = __float2bfloat16_rn(xs[u] - __bfloat162float(h[u]));
            }
            *(__nv_bfloat162*)&sAh[r][c4]     = __nv_bfloat162(h[0], h[1]);
            *(__nv_bfloat162*)&sAh[r][c4 + 2] = __nv_bfloat162(h[2], h[3]);
            *(__nv_bfloat162*)&sAl[r][c4]     = __nv_bfloat162(lo[0], lo[1]);
            *(__nv_bfloat162*)&sAl[r][c4 + 2] = __nv_bfloat162(lo[2], lo[3]);
        }
#pragma unroll
        for (int j = 0; j < 8; j++) {
            float x0 = rB[2 * j], x1 = rB[2 * j + 1];
            __nv_bfloat16 h0 = __float2bfloat16_rn(x0);
            __nv_bfloat16 h1 = __float2bfloat16_rn(x1);
            __nv_bfloat16 l0 = __float2bfloat16_rn(x0 - __bfloat162float(h0));
            __nv_bfloat16 l1 = __float2bfloat16_rn(x1 - __bfloat162float(h1));
            *(__nv_bfloat162*)&sBh[bn][bkh + 2 * j] = __nv_bfloat162(h0, h1);
            *(__nv_bfloat162*)&sBl[bn][bkh + 2 * j] = __nv_bfloat162(l0, l1);
        }
        __syncthreads();

        // prefetch next stage into regs (overlaps with compute below)
        if (s + 1 < nstages) {
            int k0 = (s + 1) * GBK;
#pragma unroll
            for (int l = 0; l < 4; l++) {
                int e = tid + l * 256;
                int gm = row0 + (e >> 3);
                int kq = (e & 7) * 4;
                rA[l] = make_float4(0.f, 0.f, 0.f, 0.f);
                if (gm < M) rA[l] = *(const float4*)(A + (size_t)gm * K + k0 + kq);
            }
            const float* bp = Bm + (size_t)(k0 + bkh) * N + col0 + bn;
#pragma unroll
            for (int kk = 0; kk < 16; kk++) rB[kk] = bp[(size_t)kk * N];
        }

        // compute: 2 k-steps of k16
#pragma unroll
        for (int ks = 0; ks < 2; ks++) {
            int kb = ks * 16;
            uint32_t ah[16], al[16], bh[8], bl[8];
#pragma unroll
            for (int mi = 0; mi < 4; mi++) {
                int mr = warp_m * 64 + mi * 16 + laneRA;
                uint32_t off = (uint32_t)(mr * APITCH + kb + laneKA) * 2;
                ldsm4(ah + mi * 4, aHiB + off);
                ldsm4(al + mi * 4, aLoB + off);
            }
#pragma unroll
            for (int bj = 0; bj < 2; bj++) {
                int nr = warp_n * 32 + bj * 16 + laneRB;
                uint32_t off = (uint32_t)(nr * APITCH + kb + laneKB) * 2;
                ldsm4(bh + bj * 4, bHiB + off);
                ldsm4(bl + bj * 4, bLoB + off);
            }
#pragma unroll
            for (int mi = 0; mi < 4; mi++)
#pragma unroll
                for (int nj = 0; nj < 4; nj++) {
                    mma_bf16(acc[mi][nj], ah + mi * 4, bh + nj * 2);
                    mma_bf16(acc[mi][nj], ah + mi * 4, bl + nj * 2);
                    mma_bf16(acc[mi][nj], al + mi * 4, bh + nj * 2);
                }
        }
    }

    // ---------------- epilogue ----------------
    int quad = lane >> 2, tq = lane & 3;
#pragma unroll
    for (int mi = 0; mi < 4; mi++) {
#pragma unroll
        for (int half = 0; half < 2; half++) {
            int gr = row0 + warp_m * 64 + mi * 16 + quad + half * 8;
            if (gr >= M) continue;
#pragma unroll
            for (int nj = 0; nj < 4; nj++) {
                int gc = col0 + warp_n * 32 + nj * 8 + tq * 2;
                float v0 = acc[mi][nj][half * 2 + 0];
                float v1 = acc[mi][nj][half * 2 + 1];
                if (bias) { v0 += bias[gc]; v1 += bias[gc + 1]; }
                if (do_gelu) {
                    v0 = 0.5f * v0 * (1.0f + erff(v0 * 0.70710678118f));
                    v1 = 0.5f * v1 * (1.0f + erff(v1 * 0.70710678118f));
                }
                if (resid) {
                    const float* rp = resid + (size_t)gr * N + gc;
                    v0 += rp[0]; v1 += rp[1];
                }
                *(float2*)(C + (size_t)gr * N + gc) = make_float2(v0, v1);
            }
        }
    }
}

// ---------------- flash attention with fused mask ----------------
#define KCH 32
#define NCHUNK ((SEQ + KCH - 1) / KCH)   // 36
__global__ void __launch_bounds__(256) attn_kernel(const float* __restrict__ qkv,
                                                   const float* __restrict__ mask,
                                                   float* __restrict__ out) {
    int qt = blockIdx.x;
    int h = blockIdx.y;
    int b = blockIdx.z;
    int q0 = qt * 64;
    int tid = threadIdx.x;

    __shared__ float Qs[64][65];
    __shared__ float Ks[KCH][65];
    __shared__ float Vs[KCH][65];
    __shared__ float Ps[64][KCH + 1];

#pragma unroll
    for (int l = 0; l < 4; l++) {
        int idx = tid + l * 256;
        int r = idx >> 4;
        int c4 = (idx & 15) * 4;
        int s = q0 + r;
        float4 qv = make_float4(0.f, 0.f, 0.f, 0.f);
        if (s < SEQ)
            qv = *(const float4*)(qkv + (size_t)(b * SEQ + s) * 3072 + h * 64 + c4);
        Qs[r][c4 + 0] = qv.x; Qs[r][c4 + 1] = qv.y;
        Qs[r][c4 + 2] = qv.z; Qs[r][c4 + 3] = qv.w;
    }

    int r = tid >> 2;
    int q = tid & 3;
    int cs = q * 8;
    int co = q * 16;
    int qrow = q0 + r;
    bool isquery = (qrow >= NUM_P) && (qrow < SEQ);
    const float* mrow = mask + ((size_t)b * NUM_Q + (qrow - NUM_P)) * NUM_P;

    float O[16];
#pragma unroll
    for (int j = 0; j < 16; j++) O[j] = 0.f;
    float m_prev = -1e30f, lsum_tot = 0.f;

    for (int chunk = 0; chunk < NCHUNK; chunk++) {
        int c0 = chunk * KCH;
        __syncthreads();
        {
            int idx = tid;
#pragma unroll
            for (int l = 0; l < 2; l++) {
                int e = idx + l * 256;
                int rr = e >> 4;
                int c4 = (e & 15) * 4;
                int s = c0 + rr;
                float4 kv = make_float4(0.f, 0.f, 0.f, 0.f);
                float4 vv = make_float4(0.f, 0.f, 0.f, 0.f);
                if (s < SEQ) {
                    const float* base = qkv + (size_t)(b * SEQ + s) * 3072 + h * 64 + c4;
                    kv = *(const float4*)(base + 1024);
                    vv = *(const float4*)(base + 2048);
                }
                Ks[rr][c4 + 0] = kv.x; Ks[rr][c4 + 1] = kv.y;
                Ks[rr][c4 + 2] = kv.z; Ks[rr][c4 + 3] = kv.w;
                Vs[rr][c4 + 0] = vv.x; Vs[rr][c4 + 1] = vv.y;
                Vs[rr][c4 + 2] = vv.z; Vs[rr][c4 + 3] = vv.w;
            }
        }
        __syncthreads();

        float sc[8];
#pragma unroll
        for (int j = 0; j < 8; j++) sc[j] = 0.f;
        for (int d = 0; d < 64; d++) {
            float qv = Qs[r][d];
#pragma unroll
            for (int j = 0; j < 8; j++) sc[j] = fmaf(qv, Ks[cs + j][d], sc[j]);
        }
#pragma unroll
        for (int j = 0; j < 8; j++) {
            int kcol = c0 + cs + j;
            float v = sc[j] * 0.125f;
            if (kcol >= SEQ) {
                v = -1e30f;
            } else if (isquery && kcol < NUM_P) {
                if (!(mrow[kcol] > 0.5f)) v = -1e9f;
            }
            sc[j] = v;
        }
        float mx = -1e30f;
#pragma unroll
        for (int j = 0; j < 8; j++) mx = fmaxf(mx, sc[j]);
        mx = fmaxf(mx, __shfl_xor_sync(0xffffffffu, mx, 1));
        mx = fmaxf(mx, __shfl_xor_sync(0xffffffffu, mx, 2));
        float m_new = fmaxf(m_prev, mx);
        float ls = 0.f;
#pragma unroll
        for (int j = 0; j < 8; j++) {
            float p = __expf(sc[j] - m_new);
            Ps[r][cs + j] = p;
            ls += p;
        }
        ls += __shfl_xor_sync(0xffffffffu, ls, 1);
        ls += __shfl_xor_sync(0xffffffffu, ls, 2);
        float alpha = __expf(m_prev - m_new);
        lsum_tot = lsum_tot * alpha + ls;
        m_prev = m_new;
#pragma unroll
        for (int j = 0; j < 16; j++) O[j] *= alpha;
        __syncwarp();
        for (int c = 0; c < KCH; c++) {
            float p = Ps[r][c];
#pragma unroll
            for (int j = 0; j < 16; j++) O[j] = fmaf(p, Vs[c][co + j], O[j]);
        }
    }

    if (qrow < SEQ) {
        float invl = 1.0f / lsum_tot;
        float* orow = out + (size_t)(b * SEQ + qrow) * EMB + h * 64 + co;
#pragma unroll
        for (int j = 0; j < 16; j++) orow[j] = O[j] * invl;
    }
}

// ---------------- launch ----------------
extern "C" void kernel_launch(void* const* d_in, const int* in_sizes, int n_in,
                              void* d_out, int out_size) {
    const float* x      = (const float*)d_in[0];
    const float* mask   = (const float*)d_in[1];
    const float* qkv_w  = (const float*)d_in[2];
    const float* proj_w = (const float*)d_in[3];
    const float* proj_b = (const float*)d_in[4];
    const float* ln1_g  = (const float*)d_in[5];
    const float* ln1_b  = (const float*)d_in[6];
    const float* ln2_g  = (const float*)d_in[7];
    const float* ln2_b  = (const float*)d_in[8];
    const float* fc1_w  = (const float*)d_in[9];
    const float* fc1_b  = (const float*)d_in[10];
    const float* fc2_w  = (const float*)d_in[11];
    const float* fc2_b  = (const float*)d_in[12];
    float* out = (float*)d_out;

    void *p_xn, *p_qkv, *p_attn, *p_x1, *p_h;
    cudaGetSymbolAddress(&p_xn, g_xn);
    cudaGetSymbolAddress(&p_qkv, g_qkv);
    cudaGetSymbolAddress(&p_attn, g_attn);
    cudaGetSymbolAddress(&p_x1, g_x1);
    cudaGetSymbolAddress(&p_h, g_h);
    float* xn = (float*)p_xn;
    float* qkv = (float*)p_qkv;
    float* attn = (float*)p_attn;
    float* x1 = (float*)p_x1;
    float* hbuf = (float*)p_h;

    const int MG = (M_ROWS + GBM - 1) / GBM;  // 71

    // 1) LN1
    ln_kernel<<<M_ROWS, 256>>>(x, ln1_g, ln1_b, xn);
    // 2) QKV GEMM: [8992,1024] @ [1024,3072]
    gemm_mma_kernel<<<dim3(3 * EMB / GBN, MG), 256>>>(xn, qkv_w, qkv, M_ROWS, 3 * EMB, EMB,
                                                      nullptr, nullptr, 0);
    // 3) attention
    attn_kernel<<<dim3(18, NH, B_), 256>>>(qkv, mask, attn);
    // 4) proj + bias + residual(x) -> x1
    gemm_mma_kernel<<<dim3(EMB / GBN, MG), 256>>>(attn, proj_w, x1, M_ROWS, EMB, EMB,
                                                  proj_b, x, 0);
    // 5) LN2
    ln_kernel<<<M_ROWS, 256>>>(x1, ln2_g, ln2_b, xn);
    // 6) fc1 + bias + gelu
    gemm_mma_kernel<<<dim3(MLP / GBN, MG), 256>>>(xn, fc1_w, hbuf, M_ROWS, MLP, EMB,
                                                  fc1_b, nullptr, 1);
    // 7) fc2 + bias + residual(x1) -> out
    gemm_mma_kernel<<<dim3(EMB / GBN, MG), 256>>>(hbuf, fc2_w, out, M_ROWS, EMB, MLP,
                                                  fc2_b, x1, 0);
}

// round 6
// speedup vs baseline: 1.3765x; 1.0011x over previous
#include <cuda_runtime.h>
#include <cuda_bf16.h>
#include <math.h>
#include <stdint.h>

#define B_ 8
#define SEQ 1124
#define EMB 1024
#define NH 16
#define HD 64
#define MLP 4096
#define M_ROWS (B_ * SEQ)          // 8992
#define NUM_Q 100
#define NUM_P 1024

// ---------------- scratch (device globals; no allocation allowed) ----------------
__device__ float g_xn[(size_t)M_ROWS * EMB];
__device__ float g_qkv[(size_t)M_ROWS * 3 * EMB];
__device__ float g_attn[(size_t)M_ROWS * EMB];
__device__ float g_x1[(size_t)M_ROWS * EMB];
__device__ float g_h[(size_t)M_ROWS * MLP];

// ---------------- helpers ----------------
__device__ __forceinline__ uint32_t smem_u32(const void* p) {
    uint32_t a;
    asm("{ .reg .u64 t; cvta.to.shared.u64 t, %1; cvt.u32.u64 %0, t; }" : "=r"(a) : "l"(p));
    return a;
}
__device__ __forceinline__ void ldsm4(uint32_t* r, uint32_t addr) {
    asm volatile("ldmatrix.sync.aligned.m8n8.x4.shared.b16 {%0,%1,%2,%3}, [%4];"
        : "=r"(r[0]), "=r"(r[1]), "=r"(r[2]), "=r"(r[3]) : "r"(addr));
}
__device__ __forceinline__ void mma_bf16(float* d, const uint32_t* a, const uint32_t* b) {
    asm volatile("mma.sync.aligned.m16n8k16.row.col.f32.bf16.bf16.f32 "
        "{%0,%1,%2,%3}, {%4,%5,%6,%7}, {%8,%9}, {%0,%1,%2,%3};"
        : "+f"(d[0]), "+f"(d[1]), "+f"(d[2]), "+f"(d[3])
        : "r"(a[0]), "r"(a[1]), "r"(a[2]), "r"(a[3]), "r"(b[0]), "r"(b[1]));
}

// ---------------- LayerNorm ----------------
__global__ void __launch_bounds__(256) ln_kernel(const float* __restrict__ x,
                                                 const float* __restrict__ g,
                                                 const float* __restrict__ b,
                                                 float* __restrict__ out) {
    int row = blockIdx.x;
    const float* xr = x + (size_t)row * EMB;
    int t = threadIdx.x;
    float v[4];
    float s = 0.f, s2 = 0.f;
#pragma unroll
    for (int i = 0; i < 4; i++) {
        float val = xr[t + i * 256];
        v[i] = val;
        s += val;
        s2 += val * val;
    }
#pragma unroll
    for (int o = 16; o > 0; o >>= 1) {
        s += __shfl_xor_sync(0xffffffffu, s, o);
        s2 += __shfl_xor_sync(0xffffffffu, s2, o);
    }
    __shared__ float red[2][8];
    int w = t >> 5, lane = t & 31;
    if (lane == 0) { red[0][w] = s; red[1][w] = s2; }
    __syncthreads();
    float ts = 0.f, ts2 = 0.f;
#pragma unroll
    for (int i = 0; i < 8; i++) { ts += red[0][i]; ts2 += red[1][i]; }
    float mean = ts * (1.0f / EMB);
    float var = ts2 * (1.0f / EMB) - mean * mean;
    float inv = rsqrtf(var + 1e-6f);
    float* orow = out + (size_t)row * EMB;
#pragma unroll
    for (int i = 0; i < 4; i++) {
        int c = t + i * 256;
        orow[c] = (v[i] - mean) * inv * g[c] + b[c];
    }
}

// ---------------- mma.sync bf16 (3x split) GEMM, tile 128x128x32 ----------------
// C[M,N] = A[M,K] @ B[K,N] (+bias) (gelu?) (+resid)
#define GBM 128
#define GBN 128
#define GBK 32
#define APITCH 40   // bf16 elems per smem row (80B, conflict-free ldmatrix)

__global__ void __launch_bounds__(256) gemm_mma_kernel(const float* __restrict__ A,
                                                       const float* __restrict__ Bm,
                                                       float* __restrict__ C,
                                                       int M, int N, int K,
                                                       const float* __restrict__ bias,
                                                       const float* __restrict__ resid,
                                                       int do_gelu) {
    __shared__ __nv_bfloat16 sAh[GBM][APITCH];
    __shared__ __nv_bfloat16 sAl[GBM][APITCH];
    __shared__ __nv_bfloat16 sBh[GBN][APITCH];   // [n][k]
    __shared__ __nv_bfloat16 sBl[GBN][APITCH];

    int tid = threadIdx.x;
    int lane = tid & 31, wid = tid >> 5;
    int warp_m = wid >> 2;          // 0..1  -> 64 rows
    int warp_n = wid & 3;           // 0..3  -> 32 cols
    int row0 = blockIdx.y * GBM;
    int col0 = blockIdx.x * GBN;

    // ldmatrix lane address components
    int laneRA = (lane & 7) + ((lane >> 3) & 1) * 8;
    int laneKA = ((lane >> 4) & 1) * 8;
    int laneRB = (lane & 7) + ((lane >> 4) & 1) * 8;
    int laneKB = ((lane >> 3) & 1) * 8;
    uint32_t aHiB = smem_u32(&sAh[0][0]);
    uint32_t aLoB = smem_u32(&sAl[0][0]);
    uint32_t bHiB = smem_u32(&sBh[0][0]);
    uint32_t bLoB = smem_u32(&sBl[0][0]);

    // global load indices
    int bn = tid >> 1;
    int bkh = (tid & 1) * 16;

    float acc[4][4][4];
#pragma unroll
    for (int i = 0; i < 4; i++)
#pragma unroll
        for (int j = 0; j < 4; j++)
#pragma unroll
            for (int r = 0; r < 4; r++) acc[i][j][r] = 0.f;

    float4 rA[4];
    float rB[16];

    // prefetch stage 0
    {
#pragma unroll
        for (int l = 0; l < 4; l++) {
            int e = tid + l * 256;
            int gm = row0 + (e >> 3);
            int kq = (e & 7) * 4;
            rA[l] = make_float4(0.f, 0.f, 0.f, 0.f);
            if (gm < M) rA[l] = *(const float4*)(A + (size_t)gm * K + kq);
        }
        const float* bp = Bm + (size_t)bkh * N + col0 + bn;
#pragma unroll
        for (int kk = 0; kk < 16; kk++) rB[kk] = bp[(size_t)kk * N];
    }

    int nstages = K / GBK;
    for (int s = 0; s < nstages; s++) {
        __syncthreads();
        // store regs -> smem with bf16 hi/lo split
#pragma unroll
        for (int l = 0; l < 4; l++) {
            int e = tid + l * 256;
            int r = e >> 3;
            int c4 = (e & 7) * 4;
            float xs[4] = {rA[l].x, rA[l].y, rA[l].z, rA[l].w};
            __nv_bfloat16 h[4], lo[4];
#pragma unroll
            for (int u = 0; u < 4; u++) {
                h[u] = __float2bfloat16_rn(xs[u]);
                lo[u] = __float2bfloat16_rn(xs[u] - __bfloat162float(h[u]));
            }
            *(__nv_bfloat162*)&sAh[r][c4]     = __nv_bfloat162(h[0], h[1]);
            *(__nv_bfloat162*)&sAh[r][c4 + 2] = __nv_bfloat162(h[2], h[3]);
            *(__nv_bfloat162*)&sAl[r][c4]     = __nv_bfloat162(lo[0], lo[1]);
            *(__nv_bfloat162*)&sAl[r][c4 + 2] = __nv_bfloat162(lo[2], lo[3]);
        }
#pragma unroll
        for (int j = 0; j < 8; j++) {
            float x0 = rB[2 * j], x1 = rB[2 * j + 1];
            __nv_bfloat16 h0 = __float2bfloat16_rn(x0);
            __nv_bfloat16 h1 = __float2bfloat16_rn(x1);
            __nv_bfloat16 l0 = __float2bfloat16_rn(x0 - __bfloat162float(h0));
            __nv_bfloat16 l1 = __float2bfloat16_rn(x1 - __bfloat162float(h1));
            *(__nv_bfloat162*)&sBh[bn][bkh + 2 * j] = __nv_bfloat162(h0, h1);
            *(__nv_bfloat162*)&sBl[bn][bkh + 2 * j] = __nv_bfloat162(l0, l1);
        }
        __syncthreads();

        // prefetch next stage into regs (overlaps with compute below)
        if (s + 1 < nstages) {
            int k0 = (s + 1) * GBK;
#pragma unroll
            for (int l = 0; l < 4; l++) {
                int e = tid + l * 256;
                int gm = row0 + (e >> 3);
                int kq = (e & 7) * 4;
                rA[l] = make_float4(0.f, 0.f, 0.f, 0.f);
                if (gm < M) rA[l] = *(const float4*)(A + (size_t)gm * K + k0 + kq);
            }
            const float* bp = Bm + (size_t)(k0 + bkh) * N + col0 + bn;
#pragma unroll
            for (int kk = 0; kk < 16; kk++) rB[kk] = bp[(size_t)kk * N];
        }

        // compute: 2 k-steps of k16
#pragma unroll
        for (int ks = 0; ks < 2; ks++) {
            int kb = ks * 16;
            uint32_t ah[16], al[16], bh[8], bl[8];
#pragma unroll
            for (int mi = 0; mi < 4; mi++) {
                int mr = warp_m * 64 + mi * 16 + laneRA;
                uint32_t off = (uint32_t)(mr * APITCH + kb + laneKA) * 2;
                ldsm4(ah + mi * 4, aHiB + off);
                ldsm4(al + mi * 4, aLoB + off);
            }
#pragma unroll
            for (int bj = 0; bj < 2; bj++) {
                int nr = warp_n * 32 + bj * 16 + laneRB;
                uint32_t off = (uint32_t)(nr * APITCH + kb + laneKB) * 2;
                ldsm4(bh + bj * 4, bHiB + off);
                ldsm4(bl + bj * 4, bLoB + off);
            }
#pragma unroll
            for (int mi = 0; mi < 4; mi++)
#pragma unroll
                for (int nj = 0; nj < 4; nj++) {
                    mma_bf16(acc[mi][nj], ah + mi * 4, bh + nj * 2);
                    mma_bf16(acc[mi][nj], ah + mi * 4, bl + nj * 2);
                    mma_bf16(acc[mi][nj], al + mi * 4, bh + nj * 2);
                }
        }
    }

    // ---------------- epilogue ----------------
    int quad = lane >> 2, tq = lane & 3;
#pragma unroll
    for (int mi = 0; mi < 4; mi++) {
#pragma unroll
        for (int half = 0; half < 2; half++) {
            int gr = row0 + warp_m * 64 + mi * 16 + quad + half * 8;
            if (gr >= M) continue;
#pragma unroll
            for (int nj = 0; nj < 4; nj++) {
                int gc = col0 + warp_n * 32 + nj * 8 + tq * 2;
                float v0 = acc[mi][nj][half * 2 + 0];
                float v1 = acc[mi][nj][half * 2 + 1];
                if (bias) { v0 += bias[gc]; v1 += bias[gc + 1]; }
                if (do_gelu) {
                    v0 = 0.5f * v0 * (1.0f + erff(v0 * 0.70710678118f));
                    v1 = 0.5f * v1 * (1.0f + erff(v1 * 0.70710678118f));
                }
                if (resid) {
                    const float* rp = resid + (size_t)gr * N + gc;
                    v0 += rp[0]; v1 += rp[1];
                }
                *(float2*)(C + (size_t)gr * N + gc) = make_float2(v0, v1);
            }
        }
    }
}

// ---------------- flash attention with fused mask ----------------
#define KCH 32
#define NCHUNK ((SEQ + KCH - 1) / KCH)   // 36
__global__ void __launch_bounds__(256) attn_kernel(const float* __restrict__ qkv,
                                                   const float* __restrict__ mask,
                                                   float* __restrict__ out) {
    int qt = blockIdx.x;
    int h = blockIdx.y;
    int b = blockIdx.z;
    int q0 = qt * 64;
    int tid = threadIdx.x;

    __shared__ float Qs[64][65];
    __shared__ float Ks[KCH][65];
    __shared__ float Vs[KCH][65];
    __shared__ float Ps[64][KCH + 1];

#pragma unroll
    for (int l = 0; l < 4; l++) {
        int idx = tid + l * 256;
        int r = idx >> 4;
        int c4 = (idx & 15) * 4;
        int s = q0 + r;
        float4 qv = make_float4(0.f, 0.f, 0.f, 0.f);
        if (s < SEQ)
            qv = *(const float4*)(qkv + (size_t)(b * SEQ + s) * 3072 + h * 64 + c4);
        Qs[r][c4 + 0] = qv.x; Qs[r][c4 + 1] = qv.y;
        Qs[r][c4 + 2] = qv.z; Qs[r][c4 + 3] = qv.w;
    }

    int r = tid >> 2;
    int q = tid & 3;
    int cs = q * 8;
    int co = q * 16;
    int qrow = q0 + r;
    bool isquery = (qrow >= NUM_P) && (qrow < SEQ);
    const float* mrow = mask + ((size_t)b * NUM_Q + (qrow - NUM_P)) * NUM_P;

    float O[16];
#pragma unroll
    for (int j = 0; j < 16; j++) O[j] = 0.f;
    float m_prev = -1e30f, lsum_tot = 0.f;

    for (int chunk = 0; chunk < NCHUNK; chunk++) {
        int c0 = chunk * KCH;
        __syncthreads();
        {
            int idx = tid;
#pragma unroll
            for (int l = 0; l < 2; l++) {
                int e = idx + l * 256;
                int rr = e >> 4;
                int c4 = (e & 15) * 4;
                int s = c0 + rr;
                float4 kv = make_float4(0.f, 0.f, 0.f, 0.f);
                float4 vv = make_float4(0.f, 0.f, 0.f, 0.f);
                if (s < SEQ) {
                    const float* base = qkv + (size_t)(b * SEQ + s) * 3072 + h * 64 + c4;
                    kv = *(const float4*)(base + 1024);
                    vv = *(const float4*)(base + 2048);
                }
                Ks[rr][c4 + 0] = kv.x; Ks[rr][c4 + 1] = kv.y;
                Ks[rr][c4 + 2] = kv.z; Ks[rr][c4 + 3] = kv.w;
                Vs[rr][c4 + 0] = vv.x; Vs[rr][c4 + 1] = vv.y;
                Vs[rr][c4 + 2] = vv.z; Vs[rr][c4 + 3] = vv.w;
            }
        }
        __syncthreads();

        float sc[8];
#pragma unroll
        for (int j = 0; j < 8; j++) sc[j] = 0.f;
        for (int d = 0; d < 64; d++) {
            float qv = Qs[r][d];
#pragma unroll
            for (int j = 0; j < 8; j++) sc[j] = fmaf(qv, Ks[cs + j][d], sc[j]);
        }
#pragma unroll
        for (int j = 0; j < 8; j++) {
            int kcol = c0 + cs + j;
            float v = sc[j] * 0.125f;
            if (kcol >= SEQ) {
                v = -1e30f;
            } else if (isquery && kcol < NUM_P) {
                if (!(mrow[kcol] > 0.5f)) v = -1e9f;
            }
            sc[j] = v;
        }
        float mx = -1e30f;
#pragma unroll
        for (int j = 0; j < 8; j++) mx = fmaxf(mx, sc[j]);
        mx = fmaxf(mx, __shfl_xor_sync(0xffffffffu, mx, 1));
        mx = fmaxf(mx, __shfl_xor_sync(0xffffffffu, mx, 2));
        float m_new = fmaxf(m_prev, mx);
        float ls = 0.f;
#pragma unroll
        for (int j = 0; j < 8; j++) {
            float p = __expf(sc[j] - m_new);
            Ps[r][cs + j] = p;
            ls += p;
        }
        ls += __shfl_xor_sync(0xffffffffu, ls, 1);
        ls += __shfl_xor_sync(0xffffffffu, ls, 2);
        float alpha = __expf(m_prev - m_new);
        lsum_tot = lsum_tot * alpha + ls;
        m_prev = m_new;
#pragma unroll
        for (int j = 0; j < 16; j++) O[j] *= alpha;
        __syncwarp();
        for (int c = 0; c < KCH; c++) {
            float p = Ps[r][c];
#pragma unroll
            for (int j = 0; j < 16; j++) O[j] = fmaf(p, Vs[c][co + j], O[j]);
        }
    }

    if (qrow < SEQ) {
        float invl = 1.0f / lsum_tot;
        float* orow = out + (size_t)(b * SEQ + qrow) * EMB + h * 64 + co;
#pragma unroll
        for (int j = 0; j < 16; j++) orow[j] = O[j] * invl;
    }
}

// ---------------- launch ----------------
extern "C" void kernel_launch(void* const* d_in, const int* in_sizes, int n_in,
                              void* d_out, int out_size) {
    const float* x      = (const float*)d_in[0];
    const float* mask   = (const float*)d_in[1];
    const float* qkv_w  = (const float*)d_in[2];
    const float* proj_w = (const float*)d_in[3];
    const float* proj_b = (const float*)d_in[4];
    const float* ln1_g  = (const float*)d_in[5];
    const float* ln1_b  = (const float*)d_in[6];
    const float* ln2_g  = (const float*)d_in[7];
    const float* ln2_b  = (const float*)d_in[8];
    const float* fc1_w  = (const float*)d_in[9];
    const float* fc1_b  = (const float*)d_in[10];
    const float* fc2_w  = (const float*)d_in[11];
    const float* fc2_b  = (const float*)d_in[12];
    float* out = (float*)d_out;

    void *p_xn, *p_qkv, *p_attn, *p_x1, *p_h;
    cudaGetSymbolAddress(&p_xn, g_xn);
    cudaGetSymbolAddress(&p_qkv, g_qkv);
    cudaGetSymbolAddress(&p_attn, g_attn);
    cudaGetSymbolAddress(&p_x1, g_x1);
    cudaGetSymbolAddress(&p_h, g_h);
    float* xn = (float*)p_xn;
    float* qkv = (float*)p_qkv;
    float* attn = (float*)p_attn;
    float* x1 = (float*)p_x1;
    float* hbuf = (float*)p_h;

    const int MG = (M_ROWS + GBM - 1) / GBM;  // 71

    // 1) LN1
    ln_kernel<<<M_ROWS, 256>>>(x, ln1_g, ln1_b, xn);
    // 2) QKV GEMM: [8992,1024] @ [1024,3072]
    gemm_mma_kernel<<<dim3(3 * EMB / GBN, MG), 256>>>(xn, qkv_w, qkv, M_ROWS, 3 * EMB, EMB,
                                                      nullptr, nullptr, 0);
    // 3) attention
    attn_kernel<<<dim3(18, NH, B_), 256>>>(qkv, mask, attn);
    // 4) proj + bias + residual(x) -> x1
    gemm_mma_kernel<<<dim3(EMB / GBN, MG), 256>>>(attn, proj_w, x1, M_ROWS, EMB, EMB,
                                                  proj_b, x, 0);
    // 5) LN2
    ln_kernel<<<M_ROWS, 256>>>(x1, ln2_g, ln2_b, xn);
    // 6) fc1 + bias + gelu
    gemm_mma_kernel<<<dim3(MLP / GBN, MG), 256>>>(xn, fc1_w, hbuf, M_ROWS, MLP, EMB,
                                                  fc1_b, nullptr, 1);
    // 7) fc2 + bias + residual(x1) -> out
    gemm_mma_kernel<<<dim3(EMB / GBN, MG), 256>>>(hbuf, fc2_w, out, M_ROWS, EMB, MLP,
                                                  fc2_b, x1, 0);
}

// round 8
// speedup vs baseline: 1.5026x; 1.0916x over previous
#include <cuda_runtime.h>
#include <cuda_bf16.h>
#include <math.h>
#include <stdint.h>

#define B_ 8
#define SEQ 1124
#define EMB 1024
#define NH 16
#define HD 64
#define MLP 4096
#define M_ROWS (B_ * SEQ)          // 8992
#define NUM_Q 100
#define NUM_P 1024

// ---------------- scratch (device globals; no allocation allowed) ----------------
__device__ float g_qkv[(size_t)M_ROWS * 3 * EMB];
__device__ float g_x1[(size_t)M_ROWS * EMB];
// activation bf16 hi/lo pairs
__device__ __nv_bfloat16 g_xnh[(size_t)M_ROWS * EMB];
__device__ __nv_bfloat16 g_xnl[(size_t)M_ROWS * EMB];
__device__ __nv_bfloat16 g_ath[(size_t)M_ROWS * EMB];
__device__ __nv_bfloat16 g_atl[(size_t)M_ROWS * EMB];
__device__ __nv_bfloat16 g_hh[(size_t)M_ROWS * MLP];
__device__ __nv_bfloat16 g_hl[(size_t)M_ROWS * MLP];
// transposed weight bf16 hi/lo pairs ([N][K] layout)
__device__ __nv_bfloat16 g_wqh[(size_t)3 * EMB * EMB];
__device__ __nv_bfloat16 g_wql[(size_t)3 * EMB * EMB];
__device__ __nv_bfloat16 g_wph[(size_t)EMB * EMB];
__device__ __nv_bfloat16 g_wpl[(size_t)EMB * EMB];
__device__ __nv_bfloat16 g_w1h[(size_t)MLP * EMB];
__device__ __nv_bfloat16 g_w1l[(size_t)MLP * EMB];
__device__ __nv_bfloat16 g_w2h[(size_t)EMB * MLP];
__device__ __nv_bfloat16 g_w2l[(size_t)EMB * MLP];

// ---------------- helpers ----------------
__device__ __forceinline__ uint32_t smem_u32(const void* p) {
    uint32_t a;
    asm("{ .reg .u64 t; cvta.to.shared.u64 t, %1; cvt.u32.u64 %0, t; }" : "=r"(a) : "l"(p));
    return a;
}
__device__ __forceinline__ void cp16(uint32_t dst, const void* src) {
    asm volatile("cp.async.cg.shared.global [%0], [%1], 16;" :: "r"(dst), "l"(src) : "memory");
}
__device__ __forceinline__ void cp_commit() { asm volatile("cp.async.commit_group;" ::: "memory"); }
template <int NN>
__device__ __forceinline__ void cp_wait() { asm volatile("cp.async.wait_group %0;" :: "n"(NN) : "memory"); }
__device__ __forceinline__ void ldsm4(uint32_t* r, uint32_t addr) {
    asm volatile("ldmatrix.sync.aligned.m8n8.x4.shared.b16 {%0,%1,%2,%3}, [%4];"
        : "=r"(r[0]), "=r"(r[1]), "=r"(r[2]), "=r"(r[3]) : "r"(addr));
}
__device__ __forceinline__ void mma_bf16(float* d, const uint32_t* a, const uint32_t* b) {
    asm volatile("mma.sync.aligned.m16n8k16.row.col.f32.bf16.bf16.f32 "
        "{%0,%1,%2,%3}, {%4,%5,%6,%7}, {%8,%9}, {%0,%1,%2,%3};"
        : "+f"(d[0]), "+f"(d[1]), "+f"(d[2]), "+f"(d[3])
        : "r"(a[0]), "r"(a[1]), "r"(a[2]), "r"(a[3]), "r"(b[0]), "r"(b[1]));
}
__device__ __forceinline__ void split_bf16(float x, __nv_bfloat16& h, __nv_bfloat16& l) {
    h = __float2bfloat16_rn(x);
    l = __float2bfloat16_rn(x - __bfloat162float(h));
}

// ---------------- weight convert + transpose: W[K][N] fp32 -> Th/Tl[N][K] bf16 ----------------
__global__ void __launch_bounds__(256) wconv_kernel(const float* __restrict__ W,
                                                    __nv_bfloat16* __restrict__ Th,
                                                    __nv_bfloat16* __restrict__ Tl,
                                                    int K, int N) {
    __shared__ float ts[32][33];
    int n0 = blockIdx.x * 32, k0 = blockIdx.y * 32;
    int tx = threadIdx.x, ty = threadIdx.y;
#pragma unroll
    for (int i = 0; i < 4; i++)
        ts[ty + 8 * i][tx] = W[(size_t)(k0 + ty + 8 * i) * N + n0 + tx];
    __syncthreads();
#pragma unroll
    for (int i = 0; i < 4; i++) {
        float v = ts[tx][ty + 8 * i];
        __nv_bfloat16 h, l;
        split_bf16(v, h, l);
        size_t o = (size_t)(n0 + ty + 8 * i) * K + k0 + tx;
        Th[o] = h; Tl[o] = l;
    }
}

// ---------------- LayerNorm -> bf16 hi/lo pairs ----------------
__global__ void __launch_bounds__(256) ln_kernel(const float* __restrict__ x,
                                                 const float* __restrict__ g,
                                                 const float* __restrict__ b,
                                                 __nv_bfloat16* __restrict__ oh,
                                                 __nv_bfloat16* __restrict__ ol) {
    int row = blockIdx.x;
    const float* xr = x + (size_t)row * EMB;
    int t = threadIdx.x;
    float v[4];
    float s = 0.f, s2 = 0.f;
#pragma unroll
    for (int i = 0; i < 4; i++) {
        float val = xr[t + i * 256];
        v[i] = val;
        s += val;
        s2 += val * val;
    }
#pragma unroll
    for (int o = 16; o > 0; o >>= 1) {
        s += __shfl_xor_sync(0xffffffffu, s, o);
        s2 += __shfl_xor_sync(0xffffffffu, s2, o);
    }
    __shared__ float red[2][8];
    int w = t >> 5, lane = t & 31;
    if (lane == 0) { red[0][w] = s; red[1][w] = s2; }
    __syncthreads();
    float ts = 0.f, ts2 = 0.f;
#pragma unroll
    for (int i = 0; i < 8; i++) { ts += red[0][i]; ts2 += red[1][i]; }
    float mean = ts * (1.0f / EMB);
    float var = ts2 * (1.0f / EMB) - mean * mean;
    float inv = rsqrtf(var + 1e-6f);
#pragma unroll
    for (int i = 0; i < 4; i++) {
        int c = t + i * 256;
        float y = (v[i] - mean) * inv * g[c] + b[c];
        __nv_bfloat16 h, l;
        split_bf16(y, h, l);
        oh[(size_t)row * EMB + c] = h;
        ol[(size_t)row * EMB + c] = l;
    }
}

// ---------------- bf16 pair GEMM, cp.async 2-stage pipeline, tile 128x128x64 ----------------
// C[M,N] = (Ah+Al)[M,K] @ (Bh+Bl)^T[N,K]^T  (3-term), epilogue bias/gelu/resid,
// output fp32 C or bf16 pair (Ch, Cl).
#define GBM 128
#define GBN 128
#define GBK 64
#define PITCH 72                       // bf16 elems per smem row (144B)
#define ARR_BYTES (128 * PITCH * 2)    // 18432
#define OFA_H 0
#define OFA_L (ARR_BYTES)
#define OFB_H (2 * ARR_BYTES)
#define OFB_L (3 * ARR_BYTES)
#define STAGE_BYTES (4 * ARR_BYTES)    // 73728
#define GEMM_SMEM (2 * STAGE_BYTES)    // 147456

__global__ void __launch_bounds__(256) gemm2_kernel(const __nv_bfloat16* __restrict__ Ah,
                                                    const __nv_bfloat16* __restrict__ Al,
                                                    const __nv_bfloat16* __restrict__ Bh,
                                                    const __nv_bfloat16* __restrict__ Bl,
                                                    float* __restrict__ C,
                                                    __nv_bfloat16* __restrict__ Ch,
                                                    __nv_bfloat16* __restrict__ Cl,
                                                    int M, int N, int K,
                                                    const float* __restrict__ bias,
                                                    const float* __restrict__ resid,
                                                    int do_gelu) {
    extern __shared__ char dsm[];
    uint32_t sb = smem_u32(dsm);
    int tid = threadIdx.x;
    int lane = tid & 31, wid = tid >> 5;
    int warp_m = wid >> 2;          // 0..1 -> 64 rows
    int warp_n = wid & 3;           // 0..3 -> 32 cols
    int row0 = blockIdx.y * GBM;
    int col0 = blockIdx.x * GBN;

    int laneRA = (lane & 7) + ((lane >> 3) & 1) * 8;
    int laneKA = ((lane >> 4) & 1) * 8;
    int laneRB = (lane & 7) + ((lane >> 4) & 1) * 8;
    int laneKB = ((lane >> 3) & 1) * 8;

    float acc[4][4][4];
#pragma unroll
    for (int i = 0; i < 4; i++)
#pragma unroll
        for (int j = 0; j < 4; j++)
#pragma unroll
            for (int r = 0; r < 4; r++) acc[i][j][r] = 0.f;

    // per-thread cp.async chunk coords (4 chunks per array)
    // chunk c = tid + t*256: row = c>>3 (0..127), col16 = c&7 (8 x 16B per row)
    auto load_stage = [&](int buf, int k0) {
        uint32_t base = sb + buf * STAGE_BYTES;
#pragma unroll
        for (int t = 0; t < 4; t++) {
            int c = tid + t * 256;
            int row = c >> 3;
            int col = c & 7;
            uint32_t doff = (uint32_t)(row * 144 + col * 16);
            int gm = row0 + row; if (gm >= M) gm = M - 1;
            size_t aoff = (size_t)gm * K + k0 + col * 8;
            cp16(base + OFA_H + doff, Ah + aoff);
            cp16(base + OFA_L + doff, Al + aoff);
            int gn = col0 + row;
            size_t boff = (size_t)gn * K + k0 + col * 8;
            cp16(base + OFB_H + doff, Bh + boff);
            cp16(base + OFB_L + doff, Bl + boff);
        }
        cp_commit();
    };

    int nstages = K / GBK;
    load_stage(0, 0);

    for (int s = 0; s < nstages; s++) {
        int buf = s & 1;
        if (s + 1 < nstages) {
            load_stage(buf ^ 1, (s + 1) * GBK);
            cp_wait<1>();
        } else {
            cp_wait<0>();
        }
        __syncthreads();

        uint32_t base = sb + buf * STAGE_BYTES;
#pragma unroll
        for (int ks = 0; ks < 4; ks++) {
            int kb = ks * 16;
            uint32_t ah[16], al[16], bh[8], bl[8];
#pragma unroll
            for (int mi = 0; mi < 4; mi++) {
                int mr = warp_m * 64 + mi * 16 + laneRA;
                uint32_t off = (uint32_t)(mr * PITCH + kb + laneKA) * 2;
                ldsm4(ah + mi * 4, base + OFA_H + off);
                ldsm4(al + mi * 4, base + OFA_L + off);
            }
#pragma unroll
            for (int bj = 0; bj < 2; bj++) {
                int nr = warp_n * 32 + bj * 16 + laneRB;
                uint32_t off = (uint32_t)(nr * PITCH + kb + laneKB) * 2;
                ldsm4(bh + bj * 4, base + OFB_H + off);
                ldsm4(bl + bj * 4, base + OFB_L + off);
            }
#pragma unroll
            for (int mi = 0; mi < 4; mi++)
#pragma unroll
                for (int nj = 0; nj < 4; nj++) {
                    mma_bf16(acc[mi][nj], ah + mi * 4, bh + nj * 2);
                    mma_bf16(acc[mi][nj], ah + mi * 4, bl + nj * 2);
                    mma_bf16(acc[mi][nj], al + mi * 4, bh + nj * 2);
                }
        }
        __syncthreads();
    }

    // ---------------- epilogue ----------------
    int quad = lane >> 2, tq = lane & 3;
#pragma unroll
    for (int mi = 0; mi < 4; mi++) {
#pragma unroll
        for (int half = 0; half < 2; half++) {
            int gr = row0 + warp_m * 64 + mi * 16 + quad + half * 8;
            if (gr >= M) continue;
#pragma unroll
            for (int nj = 0; nj < 4; nj++) {
                int gc = col0 + warp_n * 32 + nj * 8 + tq * 2;
                float v0 = acc[mi][nj][half * 2 + 0];
                float v1 = acc[mi][nj][half * 2 + 1];
                if (bias) { v0 += bias[gc]; v1 += bias[gc + 1]; }
                if (do_gelu) {
                    v0 = 0.5f * v0 * (1.0f + erff(v0 * 0.70710678118f));
                    v1 = 0.5f * v1 * (1.0f + erff(v1 * 0.70710678118f));
                }
                if (resid) {
                    const float* rp = resid + (size_t)gr * N + gc;
                    v0 += rp[0]; v1 += rp[1];
                }
                if (Ch) {
                    __nv_bfloat16 h0, l0, h1, l1;
                    split_bf16(v0, h0, l0);
                    split_bf16(v1, h1, l1);
                    *(__nv_bfloat162*)(Ch + (size_t)gr * N + gc) = __nv_bfloat162(h0, h1);
                    *(__nv_bfloat162*)(Cl + (size_t)gr * N + gc) = __nv_bfloat162(l0, l1);
                } else {
                    *(float2*)(C + (size_t)gr * N + gc) = make_float2(v0, v1);
                }
            }
        }
    }
}

// ---------------- flash attention with fused mask; bf16-pair output ----------------
#define KCH 32
#define NCHUNK ((SEQ + KCH - 1) / KCH)   // 36
__global__ void __launch_bounds__(256) attn_kernel(const float* __restrict__ qkv,
                                                   const float* __restrict__ mask,
                                                   __nv_bfloat16* __restrict__ oh,
                                                   __nv_bfloat16* __restrict__ ol) {
    int qt = blockIdx.x;
    int h = blockIdx.y;
    int b = blockIdx.z;
    int q0 = qt * 64;
    int tid = threadIdx.x;

    __shared__ float Qs[64][65];
    __shared__ float Ks[KCH][65];
    __shared__ float Vs[KCH][65];
    __shared__ float Ps[64][KCH + 1];

#pragma unroll
    for (int l = 0; l < 4; l++) {
        int idx = tid + l * 256;
        int r = idx >> 4;
        int c4 = (idx & 15) * 4;
        int s = q0 + r;
        float4 qv = make_float4(0.f, 0.f, 0.f, 0.f);
        if (s < SEQ)
            qv = *(const float4*)(qkv + (size_t)(b * SEQ + s) * 3072 + h * 64 + c4);
        Qs[r][c4 + 0] = qv.x; Qs[r][c4 + 1] = qv.y;
        Qs[r][c4 + 2] = qv.z; Qs[r][c4 + 3] = qv.w;
    }

    int r = tid >> 2;
    int q = tid & 3;
    int cs = q * 8;
    int co = q * 16;
    int qrow = q0 + r;
    bool isquery = (qrow >= NUM_P) && (qrow < SEQ);
    const float* mrow = mask + ((size_t)b * NUM_Q + (qrow - NUM_P)) * NUM_P;

    float O[16];
#pragma unroll
    for (int j = 0; j < 16; j++) O[j] = 0.f;
    float m_prev = -1e30f, lsum_tot = 0.f;

    for (int chunk = 0; chunk < NCHUNK; chunk++) {
        int c0 = chunk * KCH;
        __syncthreads();
        {
            int idx = tid;
#pragma unroll
            for (int l = 0; l < 2; l++) {
                int e = idx + l * 256;
                int rr = e >> 4;
                int c4 = (e & 15) * 4;
                int s = c0 + rr;
                float4 kv = make_float4(0.f, 0.f, 0.f, 0.f);
                float4 vv = make_float4(0.f, 0.f, 0.f, 0.f);
                if (s < SEQ) {
                    const float* base = qkv + (size_t)(b * SEQ + s) * 3072 + h * 64 + c4;
                    kv = *(const float4*)(base + 1024);
                    vv = *(const float4*)(base + 2048);
                }
                Ks[rr][c4 + 0] = kv.x; Ks[rr][c4 + 1] = kv.y;
                Ks[rr][c4 + 2] = kv.z; Ks[rr][c4 + 3] = kv.w;
                Vs[rr][c4 + 0] = vv.x; Vs[rr][c4 + 1] = vv.y;
                Vs[rr][c4 + 2] = vv.z; Vs[rr][c4 + 3] = vv.w;
            }
        }
        __syncthreads();

        float sc[8];
#pragma unroll
        for (int j = 0; j < 8; j++) sc[j] = 0.f;
        for (int d = 0; d < 64; d++) {
            float qv = Qs[r][d];
#pragma unroll
            for (int j = 0; j < 8; j++) sc[j] = fmaf(qv, Ks[cs + j][d], sc[j]);
        }
#pragma unroll
        for (int j = 0; j < 8; j++) {
            int kcol = c0 + cs + j;
            float v = sc[j] * 0.125f;
            if (kcol >= SEQ) {
                v = -1e30f;
            } else if (isquery && kcol < NUM_P) {
                if (!(mrow[kcol] > 0.5f)) v = -1e9f;
            }
            sc[j] = v;
        }
        float mx = -1e30f;
#pragma unroll
        for (int j = 0; j < 8; j++) mx = fmaxf(mx, sc[j]);
        mx = fmaxf(mx, __shfl_xor_sync(0xffffffffu, mx, 1));
        mx = fmaxf(mx, __shfl_xor_sync(0xffffffffu, mx, 2));
        float m_new = fmaxf(m_prev, mx);
        float ls = 0.f;
#pragma unroll
        for (int j = 0; j < 8; j++) {
            float p = __expf(sc[j] - m_new);
            Ps[r][cs + j] = p;
            ls += p;
        }
        ls += __shfl_xor_sync(0xffffffffu, ls, 1);
        ls += __shfl_xor_sync(0xffffffffu, ls, 2);
        float alpha = __expf(m_prev - m_new);
        lsum_tot = lsum_tot * alpha + ls;
        m_prev = m_new;
#pragma unroll
        for (int j = 0; j < 16; j++) O[j] *= alpha;
        __syncwarp();
        for (int c = 0; c < KCH; c++) {
            float p = Ps[r][c];
#pragma unroll
            for (int j = 0; j < 16; j++) O[j] = fmaf(p, Vs[c][co + j], O[j]);
        }
    }

    if (qrow < SEQ) {
        float invl = 1.0f / lsum_tot;
        size_t obase = (size_t)(b * SEQ + qrow) * EMB + h * 64 + co;
#pragma unroll
        for (int j = 0; j < 16; j += 2) {
            float v0 = O[j] * invl, v1 = O[j + 1] * invl;
            __nv_bfloat16 h0, l0, h1, l1;
            split_bf16(v0, h0, l0);
            split_bf16(v1, h1, l1);
            *(__nv_bfloat162*)(oh + obase + j) = __nv_bfloat162(h0, h1);
            *(__nv_bfloat162*)(ol + obase + j) = __nv_bfloat162(l0, l1);
        }
    }
}

// ---------------- launch ----------------
extern "C" void kernel_launch(void* const* d_in, const int* in_sizes, int n_in,
                              void* d_out, int out_size) {
    const float* x      = (const float*)d_in[0];
    const float* mask   = (const float*)d_in[1];
    const float* qkv_w  = (const float*)d_in[2];
    const float* proj_w = (const float*)d_in[3];
    const float* proj_b = (const float*)d_in[4];
    const float* ln1_g  = (const float*)d_in[5];
    const float* ln1_b  = (const float*)d_in[6];
    const float* ln2_g  = (const float*)d_in[7];
    const float* ln2_b  = (const float*)d_in[8];
    const float* fc1_w  = (const float*)d_in[9];
    const float* fc1_b  = (const float*)d_in[10];
    const float* fc2_w  = (const float*)d_in[11];
    const float* fc2_b  = (const float*)d_in[12];
    float* out = (float*)d_out;

    void *pqkv, *px1, *pxnh, *pxnl, *path, *patl, *phh, *phl;
    void *pwqh, *pwql, *pwph, *pwpl, *pw1h, *pw1l, *pw2h, *pw2l;
    cudaGetSymbolAddress(&pqkv, g_qkv);
    cudaGetSymbolAddress(&px1, g_x1);
    cudaGetSymbolAddress(&pxnh, g_xnh);
    cudaGetSymbolAddress(&pxnl, g_xnl);
    cudaGetSymbolAddress(&path, g_ath);
    cudaGetSymbolAddress(&patl, g_atl);
    cudaGetSymbolAddress(&phh, g_hh);
    cudaGetSymbolAddress(&phl, g_hl);
    cudaGetSymbolAddress(&pwqh, g_wqh);
    cudaGetSymbolAddress(&pwql, g_wql);
    cudaGetSymbolAddress(&pwph, g_wph);
    cudaGetSymbolAddress(&pwpl, g_wpl);
    cudaGetSymbolAddress(&pw1h, g_w1h);
    cudaGetSymbolAddress(&pw1l, g_w1l);
    cudaGetSymbolAddress(&pw2h, g_w2h);
    cudaGetSymbolAddress(&pw2l, g_w2l);
    float* qkv = (float*)pqkv;
    float* x1 = (float*)px1;
    __nv_bfloat16 *xnh = (__nv_bfloat16*)pxnh, *xnl = (__nv_bfloat16*)pxnl;
    __nv_bfloat16 *ath = (__nv_bfloat16*)path, *atl = (__nv_bfloat16*)patl;
    __nv_bfloat16 *hh = (__nv_bfloat16*)phh, *hl = (__nv_bfloat16*)phl;
    __nv_bfloat16 *wqh = (__nv_bfloat16*)pwqh, *wql = (__nv_bfloat16*)pwql;
    __nv_bfloat16 *wph = (__nv_bfloat16*)pwph, *wpl = (__nv_bfloat16*)pwpl;
    __nv_bfloat16 *w1h = (__nv_bfloat16*)pw1h, *w1l = (__nv_bfloat16*)pw1l;
    __nv_bfloat16 *w2h = (__nv_bfloat16*)pw2h, *w2l = (__nv_bfloat16*)pw2l;

    cudaFuncSetAttribute(gemm2_kernel, cudaFuncAttributeMaxDynamicSharedMemorySize, GEMM_SMEM);

    const int MG = (M_ROWS + GBM - 1) / GBM;  // 71
    dim3 tb(32, 8);

    // 0) weight convert + transpose (per launch; deterministic)
    wconv_kernel<<<dim3(3 * EMB / 32, EMB / 32), tb>>>(qkv_w, wqh, wql, EMB, 3 * EMB);
    wconv_kernel<<<dim3(EMB / 32, EMB / 32), tb>>>(proj_w, wph, wpl, EMB, EMB);
    wconv_kernel<<<dim3(MLP / 32, EMB / 32), tb>>>(fc1_w, w1h, w1l, EMB, MLP);
    wconv_kernel<<<dim3(EMB / 32, MLP / 32), tb>>>(fc2_w, w2h, w2l, MLP, EMB);

    // 1) LN1 -> bf16 pairs
    ln_kernel<<<M_ROWS, 256>>>(x, ln1_g, ln1_b, xnh, xnl);
    // 2) QKV GEMM -> fp32 qkv
    gemm2_kernel<<<dim3(3 * EMB / GBN, MG), 256, GEMM_SMEM>>>(
        xnh, xnl, wqh, wql, qkv, nullptr, nullptr, M_ROWS, 3 * EMB, EMB,
        nullptr, nullptr, 0);
    // 3) attention -> bf16 pairs
    attn_kernel<<<dim3(18, NH, B_), 256>>>(qkv, mask, ath, atl);
    // 4) proj + bias + residual(x) -> fp32 x1
    gemm2_kernel<<<dim3(EMB / GBN, MG), 256, GEMM_SMEM>>>(
        ath, atl, wph, wpl, x1, nullptr, nullptr, M_ROWS, EMB, EMB,
        proj_b, x, 0);
    // 5) LN2 -> bf16 pairs
    ln_kernel<<<M_ROWS, 256>>>(x1, ln2_g, ln2_b, xnh, xnl);
    // 6) fc1 + bias + gelu -> bf16 pairs
    gemm2_kernel<<<dim3(MLP / GBN, MG), 256, GEMM_SMEM>>>(
        xnh, xnl, w1h, w1l, nullptr, hh, hl, M_ROWS, MLP, EMB,
        fc1_b, nullptr, 1);
    // 7) fc2 + bias + residual(x1) -> out
    gemm2_kernel<<<dim3(EMB / GBN, MG), 256, GEMM_SMEM>>>(
        hh, hl, w2h, w2l, out, nullptr, nullptr, M_ROWS, EMB, MLP,
        fc2_b, x1, 0);
}

// round 9
// speedup vs baseline: 3.0381x; 2.0218x over previous
#include <cuda_runtime.h>
#include <cuda_bf16.h>
#include <math.h>
#include <stdint.h>

#define B_ 8
#define SEQ 1124
#define EMB 1024
#define NH 16
#define HD 64
#define MLP 4096
#define M_ROWS (B_ * SEQ)          // 8992
#define NUM_Q 100
#define NUM_P 1024

// ---------------- scratch (device globals; no allocation allowed) ----------------
__device__ float g_qkv[(size_t)M_ROWS * 3 * EMB];
__device__ float g_x1[(size_t)M_ROWS * EMB];
// activation bf16 hi/lo pairs
__device__ __nv_bfloat16 g_xnh[(size_t)M_ROWS * EMB];
__device__ __nv_bfloat16 g_xnl[(size_t)M_ROWS * EMB];
__device__ __nv_bfloat16 g_ath[(size_t)M_ROWS * EMB];
__device__ __nv_bfloat16 g_atl[(size_t)M_ROWS * EMB];
__device__ __nv_bfloat16 g_hh[(size_t)M_ROWS * MLP];
__device__ __nv_bfloat16 g_hl[(size_t)M_ROWS * MLP];
// transposed weight bf16 hi/lo pairs ([N][K] layout)
__device__ __nv_bfloat16 g_wqh[(size_t)3 * EMB * EMB];
__device__ __nv_bfloat16 g_wql[(size_t)3 * EMB * EMB];
__device__ __nv_bfloat16 g_wph[(size_t)EMB * EMB];
__device__ __nv_bfloat16 g_wpl[(size_t)EMB * EMB];
__device__ __nv_bfloat16 g_w1h[(size_t)MLP * EMB];
__device__ __nv_bfloat16 g_w1l[(size_t)MLP * EMB];
__device__ __nv_bfloat16 g_w2h[(size_t)EMB * MLP];
__device__ __nv_bfloat16 g_w2l[(size_t)EMB * MLP];

// ---------------- helpers ----------------
__device__ __forceinline__ uint32_t smem_u32(const void* p) {
    uint32_t a;
    asm("{ .reg .u64 t; cvta.to.shared.u64 t, %1; cvt.u32.u64 %0, t; }" : "=r"(a) : "l"(p));
    return a;
}
__device__ __forceinline__ void cp16(uint32_t dst, const void* src) {
    asm volatile("cp.async.cg.shared.global [%0], [%1], 16;" :: "r"(dst), "l"(src) : "memory");
}
__device__ __forceinline__ void cp_commit() { asm volatile("cp.async.commit_group;" ::: "memory"); }
template <int NN>
__device__ __forceinline__ void cp_wait() { asm volatile("cp.async.wait_group %0;" :: "n"(NN) : "memory"); }
__device__ __forceinline__ void ldsm4(uint32_t* r, uint32_t addr) {
    asm volatile("ldmatrix.sync.aligned.m8n8.x4.shared.b16 {%0,%1,%2,%3}, [%4];"
        : "=r"(r[0]), "=r"(r[1]), "=r"(r[2]), "=r"(r[3]) : "r"(addr));
}
__device__ __forceinline__ void mma_bf16(float* d, const uint32_t* a, const uint32_t* b) {
    asm volatile("mma.sync.aligned.m16n8k16.row.col.f32.bf16.bf16.f32 "
        "{%0,%1,%2,%3}, {%4,%5,%6,%7}, {%8,%9}, {%0,%1,%2,%3};"
        : "+f"(d[0]), "+f"(d[1]), "+f"(d[2]), "+f"(d[3])
        : "r"(a[0]), "r"(a[1]), "r"(a[2]), "r"(a[3]), "r"(b[0]), "r"(b[1]));
}
__device__ __forceinline__ void split_bf16(float x, __nv_bfloat16& h, __nv_bfloat16& l) {
    h = __float2bfloat16_rn(x);
    l = __float2bfloat16_rn(x - __bfloat162float(h));
}
__device__ __forceinline__ void split_pack2(float x, float y, uint32_t& ph, uint32_t& pl) {
    __nv_bfloat16 hx, lx, hy, ly;
    split_bf16(x, hx, lx);
    split_bf16(y, hy, ly);
    __nv_bfloat162 H(hx, hy), L(lx, ly);
    ph = *(uint32_t*)&H;
    pl = *(uint32_t*)&L;
}

// ---------------- weight convert + transpose: W[K][N] fp32 -> Th/Tl[N][K] bf16 ----------------
__global__ void __launch_bounds__(256) wconv_kernel(const float* __restrict__ W,
                                                    __nv_bfloat16* __restrict__ Th,
                                                    __nv_bfloat16* __restrict__ Tl,
                                                    int K, int N) {
    __shared__ float ts[32][33];
    int n0 = blockIdx.x * 32, k0 = blockIdx.y * 32;
    int tx = threadIdx.x, ty = threadIdx.y;
#pragma unroll
    for (int i = 0; i < 4; i++)
        ts[ty + 8 * i][tx] = W[(size_t)(k0 + ty + 8 * i) * N + n0 + tx];
    __syncthreads();
#pragma unroll
    for (int i = 0; i < 4; i++) {
        float v = ts[tx][ty + 8 * i];
        __nv_bfloat16 h, l;
        split_bf16(v, h, l);
        size_t o = (size_t)(n0 + ty + 8 * i) * K + k0 + tx;
        Th[o] = h; Tl[o] = l;
    }
}

// ---------------- LayerNorm -> bf16 hi/lo pairs ----------------
__global__ void __launch_bounds__(256) ln_kernel(const float* __restrict__ x,
                                                 const float* __restrict__ g,
                                                 const float* __restrict__ b,
                                                 __nv_bfloat16* __restrict__ oh,
                                                 __nv_bfloat16* __restrict__ ol) {
    int row = blockIdx.x;
    const float* xr = x + (size_t)row * EMB;
    int t = threadIdx.x;
    float v[4];
    float s = 0.f, s2 = 0.f;
#pragma unroll
    for (int i = 0; i < 4; i++) {
        float val = xr[t + i * 256];
        v[i] = val;
        s += val;
        s2 += val * val;
    }
#pragma unroll
    for (int o = 16; o > 0; o >>= 1) {
        s += __shfl_xor_sync(0xffffffffu, s, o);
        s2 += __shfl_xor_sync(0xffffffffu, s2, o);
    }
    __shared__ float red[2][8];
    int w = t >> 5, lane = t & 31;
    if (lane == 0) { red[0][w] = s; red[1][w] = s2; }
    __syncthreads();
    float ts = 0.f, ts2 = 0.f;
#pragma unroll
    for (int i = 0; i < 8; i++) { ts += red[0][i]; ts2 += red[1][i]; }
    float mean = ts * (1.0f / EMB);
    float var = ts2 * (1.0f / EMB) - mean * mean;
    float inv = rsqrtf(var + 1e-6f);
#pragma unroll
    for (int i = 0; i < 4; i++) {
        int c = t + i * 256;
        float y = (v[i] - mean) * inv * g[c] + b[c];
        __nv_bfloat16 h, l;
        split_bf16(y, h, l);
        oh[(size_t)row * EMB + c] = h;
        ol[(size_t)row * EMB + c] = l;
    }
}

// ---------------- bf16 pair GEMM, cp.async 2-stage pipeline, tile 128x128x64 ----------------
#define GBM 128
#define GBN 128
#define GBK 64
#define PITCH 72                       // bf16 elems per smem row (144B)
#define ARR_BYTES (128 * PITCH * 2)    // 18432
#define OFA_H 0
#define OFA_L (ARR_BYTES)
#define OFB_H (2 * ARR_BYTES)
#define OFB_L (3 * ARR_BYTES)
#define STAGE_BYTES (4 * ARR_BYTES)    // 73728
#define GEMM_SMEM (2 * STAGE_BYTES)    // 147456

__global__ void __launch_bounds__(256) gemm2_kernel(const __nv_bfloat16* __restrict__ Ah,
                                                    const __nv_bfloat16* __restrict__ Al,
                                                    const __nv_bfloat16* __restrict__ Bh,
                                                    const __nv_bfloat16* __restrict__ Bl,
                                                    float* __restrict__ C,
                                                    __nv_bfloat16* __restrict__ Ch,
                                                    __nv_bfloat16* __restrict__ Cl,
                                                    int M, int N, int K,
                                                    const float* __restrict__ bias,
                                                    const float* __restrict__ resid,
                                                    int do_gelu) {
    extern __shared__ char dsm[];
    uint32_t sb = smem_u32(dsm);
    int tid = threadIdx.x;
    int lane = tid & 31, wid = tid >> 5;
    int warp_m = wid >> 2;
    int warp_n = wid & 3;
    int row0 = blockIdx.y * GBM;
    int col0 = blockIdx.x * GBN;

    int laneRA = (lane & 7) + ((lane >> 3) & 1) * 8;
    int laneKA = ((lane >> 4) & 1) * 8;
    int laneRB = (lane & 7) + ((lane >> 4) & 1) * 8;
    int laneKB = ((lane >> 3) & 1) * 8;

    float acc[4][4][4];
#pragma unroll
    for (int i = 0; i < 4; i++)
#pragma unroll
        for (int j = 0; j < 4; j++)
#pragma unroll
            for (int r = 0; r < 4; r++) acc[i][j][r] = 0.f;

    auto load_stage = [&](int buf, int k0) {
        uint32_t base = sb + buf * STAGE_BYTES;
#pragma unroll
        for (int t = 0; t < 4; t++) {
            int c = tid + t * 256;
            int row = c >> 3;
            int col = c & 7;
            uint32_t doff = (uint32_t)(row * 144 + col * 16);
            int gm = row0 + row; if (gm >= M) gm = M - 1;
            size_t aoff = (size_t)gm * K + k0 + col * 8;
            cp16(base + OFA_H + doff, Ah + aoff);
            cp16(base + OFA_L + doff, Al + aoff);
            int gn = col0 + row;
            size_t boff = (size_t)gn * K + k0 + col * 8;
            cp16(base + OFB_H + doff, Bh + boff);
            cp16(base + OFB_L + doff, Bl + boff);
        }
        cp_commit();
    };

    int nstages = K / GBK;
    load_stage(0, 0);

    for (int s = 0; s < nstages; s++) {
        int buf = s & 1;
        if (s + 1 < nstages) {
            load_stage(buf ^ 1, (s + 1) * GBK);
            cp_wait<1>();
        } else {
            cp_wait<0>();
        }
        __syncthreads();

        uint32_t base = sb + buf * STAGE_BYTES;
#pragma unroll
        for (int ks = 0; ks < 4; ks++) {
            int kb = ks * 16;
            uint32_t ah[16], al[16], bh[8], bl[8];
#pragma unroll
            for (int mi = 0; mi < 4; mi++) {
                int mr = warp_m * 64 + mi * 16 + laneRA;
                uint32_t off = (uint32_t)(mr * PITCH + kb + laneKA) * 2;
                ldsm4(ah + mi * 4, base + OFA_H + off);
                ldsm4(al + mi * 4, base + OFA_L + off);
            }
#pragma unroll
            for (int bj = 0; bj < 2; bj++) {
                int nr = warp_n * 32 + bj * 16 + laneRB;
                uint32_t off = (uint32_t)(nr * PITCH + kb + laneKB) * 2;
                ldsm4(bh + bj * 4, base + OFB_H + off);
                ldsm4(bl + bj * 4, base + OFB_L + off);
            }
#pragma unroll
            for (int mi = 0; mi < 4; mi++)
#pragma unroll
                for (int nj = 0; nj < 4; nj++) {
                    mma_bf16(acc[mi][nj], ah + mi * 4, bh + nj * 2);
                    mma_bf16(acc[mi][nj], ah + mi * 4, bl + nj * 2);
                    mma_bf16(acc[mi][nj], al + mi * 4, bh + nj * 2);
                }
        }
        __syncthreads();
    }

    int quad = lane >> 2, tq = lane & 3;
#pragma unroll
    for (int mi = 0; mi < 4; mi++) {
#pragma unroll
        for (int half = 0; half < 2; half++) {
            int gr = row0 + warp_m * 64 + mi * 16 + quad + half * 8;
            if (gr >= M) continue;
#pragma unroll
            for (int nj = 0; nj < 4; nj++) {
                int gc = col0 + warp_n * 32 + nj * 8 + tq * 2;
                float v0 = acc[mi][nj][half * 2 + 0];
                float v1 = acc[mi][nj][half * 2 + 1];
                if (bias) { v0 += bias[gc]; v1 += bias[gc + 1]; }
                if (do_gelu) {
                    v0 = 0.5f * v0 * (1.0f + erff(v0 * 0.70710678118f));
                    v1 = 0.5f * v1 * (1.0f + erff(v1 * 0.70710678118f));
                }
                if (resid) {
                    const float* rp = resid + (size_t)gr * N + gc;
                    v0 += rp[0]; v1 += rp[1];
                }
                if (Ch) {
                    __nv_bfloat16 h0, l0, h1, l1;
                    split_bf16(v0, h0, l0);
                    split_bf16(v1, h1, l1);
                    *(__nv_bfloat162*)(Ch + (size_t)gr * N + gc) = __nv_bfloat162(h0, h1);
                    *(__nv_bfloat162*)(Cl + (size_t)gr * N + gc) = __nv_bfloat162(l0, l1);
                } else {
                    *(float2*)(C + (size_t)gr * N + gc) = make_float2(v0, v1);
                }
            }
        }
    }
}

// ---------------- mma-based flash attention ----------------
// 128 q-rows per CTA (8 warps x 16 rows), K chunks of 64.
// Q,K hi/lo split in smem; V stored transposed [hd][kpos] hi/lo.
#define AT_QT 128
#define AT_KC 64
#define AT_PITCH 72
#define AT_NCH ((SEQ + AT_KC - 1) / AT_KC)          // 18
#define AOQH 0
#define AOQL (AOQH + AT_QT * AT_PITCH * 2)          // 18432
#define AOKH (AOQL + AT_QT * AT_PITCH * 2)          // 36864
#define AOKL (AOKH + AT_KC * AT_PITCH * 2)          // 46080
#define AOVH (AOKL + AT_KC * AT_PITCH * 2)          // 55296
#define AOVL (AOVH + AT_KC * AT_PITCH * 2)          // 64512
#define ATTN_SMEM (AOVL + AT_KC * AT_PITCH * 2)     // 73728

__global__ void __launch_bounds__(256) attn_mma_kernel(const float* __restrict__ qkv,
                                                       const float* __restrict__ mask,
                                                       __nv_bfloat16* __restrict__ oh,
                                                       __nv_bfloat16* __restrict__ ol) {
    extern __shared__ char dsm[];
    uint32_t sb = smem_u32(dsm);
    __nv_bfloat16* sQh = (__nv_bfloat16*)(dsm + AOQH);
    __nv_bfloat16* sQl = (__nv_bfloat16*)(dsm + AOQL);
    __nv_bfloat16* sKh = (__nv_bfloat16*)(dsm + AOKH);
    __nv_bfloat16* sKl = (__nv_bfloat16*)(dsm + AOKL);
    __nv_bfloat16* sVh = (__nv_bfloat16*)(dsm + AOVH);
    __nv_bfloat16* sVl = (__nv_bfloat16*)(dsm + AOVL);

    int qt = blockIdx.x, h = blockIdx.y, b = blockIdx.z;
    int q0 = qt * AT_QT;
    int tid = threadIdx.x;
    int lane = tid & 31, wid = tid >> 5;
    int quad = lane >> 2, tq = lane & 3;

    int laneRA = (lane & 7) + ((lane >> 3) & 1) * 8;
    int laneKA = ((lane >> 4) & 1) * 8;
    int laneRB = (lane & 7) + ((lane >> 4) & 1) * 8;
    int laneKB = ((lane >> 3) & 1) * 8;

    // load Q (scaled by 1/8, exact), split hi/lo
#pragma unroll
    for (int l = 0; l < 8; l++) {
        int e = tid + l * 256;
        int row = e >> 4;
        int c4 = (e & 15) * 4;
        int s = q0 + row;
        float4 qv = make_float4(0.f, 0.f, 0.f, 0.f);
        if (s < SEQ)
            qv = *(const float4*)(qkv + (size_t)(b * SEQ + s) * 3072 + h * 64 + c4);
        float xs[4] = {qv.x * 0.125f, qv.y * 0.125f, qv.z * 0.125f, qv.w * 0.125f};
#pragma unroll
        for (int u = 0; u < 4; u += 2) {
            __nv_bfloat16 h0, l0, h1, l1;
            split_bf16(xs[u], h0, l0);
            split_bf16(xs[u + 1], h1, l1);
            *(__nv_bfloat162*)&sQh[row * AT_PITCH + c4 + u] = __nv_bfloat162(h0, h1);
            *(__nv_bfloat162*)&sQl[row * AT_PITCH + c4 + u] = __nv_bfloat162(l0, l1);
        }
    }

    int mr0 = wid * 16;
    int r0g = q0 + mr0 + quad;
    int r1g = r0g + 8;
    bool isq0 = (r0g >= NUM_P) && (r0g < SEQ);
    bool isq1 = (r1g >= NUM_P) && (r1g < SEQ);
    const float* mrow0 = mask + ((size_t)b * NUM_Q + (isq0 ? r0g - NUM_P : 0)) * NUM_P;
    const float* mrow1 = mask + ((size_t)b * NUM_Q + (isq1 ? r1g - NUM_P : 0)) * NUM_P;

    float O[8][4];
#pragma unroll
    for (int i = 0; i < 8; i++)
#pragma unroll
        for (int j = 0; j < 4; j++) O[i][j] = 0.f;
    float m0 = -1e30f, m1 = -1e30f, l0s = 0.f, l1s = 0.f;

    for (int chunk = 0; chunk < AT_NCH; chunk++) {
        int c0 = chunk * AT_KC;
        __syncthreads();
        // load K chunk [kpos][d] and V chunk transposed [d][kpos]
#pragma unroll
        for (int l = 0; l < 4; l++) {
            int e = tid + l * 256;
            int kpos = e >> 4;
            int c4 = (e & 15) * 4;
            int s = c0 + kpos;
            float4 kv = make_float4(0.f, 0.f, 0.f, 0.f);
            float4 vv = make_float4(0.f, 0.f, 0.f, 0.f);
            if (s < SEQ) {
                const float* base = qkv + (size_t)(b * SEQ + s) * 3072 + h * 64 + c4;
                kv = *(const float4*)(base + 1024);
                vv = *(const float4*)(base + 2048);
            }
            float ks[4] = {kv.x, kv.y, kv.z, kv.w};
            float vs[4] = {vv.x, vv.y, vv.z, vv.w};
#pragma unroll
            for (int u = 0; u < 4; u += 2) {
                __nv_bfloat16 h0, lo0, h1, lo1;
                split_bf16(ks[u], h0, lo0);
                split_bf16(ks[u + 1], h1, lo1);
                *(__nv_bfloat162*)&sKh[kpos * AT_PITCH + c4 + u] = __nv_bfloat162(h0, h1);
                *(__nv_bfloat162*)&sKl[kpos * AT_PITCH + c4 + u] = __nv_bfloat162(lo0, lo1);
            }
#pragma unroll
            for (int u = 0; u < 4; u++) {
                __nv_bfloat16 hv, lv;
                split_bf16(vs[u], hv, lv);
                sVh[(c4 + u) * AT_PITCH + kpos] = hv;
                sVl[(c4 + u) * AT_PITCH + kpos] = lv;
            }
        }
        __syncthreads();

        // S = Q K^T (3-term)
        float sc[8][4];
#pragma unroll
        for (int i = 0; i < 8; i++)
#pragma unroll
            for (int j = 0; j < 4; j++) sc[i][j] = 0.f;
#pragma unroll
        for (int ks = 0; ks < 4; ks++) {
            int kb = ks * 16;
            uint32_t ah[4], al[4];
            uint32_t aoff = (uint32_t)((mr0 + laneRA) * AT_PITCH + kb + laneKA) * 2;
            ldsm4(ah, sb + AOQH + aoff);
            ldsm4(al, sb + AOQL + aoff);
#pragma unroll
            for (int bj = 0; bj < 4; bj++) {
                uint32_t boff = (uint32_t)((bj * 16 + laneRB) * AT_PITCH + kb + laneKB) * 2;
                uint32_t bh[4], bl[4];
                ldsm4(bh, sb + AOKH + boff);
                ldsm4(bl, sb + AOKL + boff);
                mma_bf16(sc[bj * 2], ah, bh);
                mma_bf16(sc[bj * 2], ah, bl);
                mma_bf16(sc[bj * 2], al, bh);
                mma_bf16(sc[bj * 2 + 1], ah, bh + 2);
                mma_bf16(sc[bj * 2 + 1], ah, bl + 2);
                mma_bf16(sc[bj * 2 + 1], al, bh + 2);
            }
        }

        // mask + online softmax
        float nm0 = m0, nm1 = m1;
#pragma unroll
        for (int nt = 0; nt < 8; nt++) {
#pragma unroll
            for (int j = 0; j < 4; j++) {
                int kcol = c0 + nt * 8 + tq * 2 + (j & 1);
                float v = sc[nt][j];
                if (kcol >= SEQ) {
                    v = -1e30f;
                } else if ((j < 2 ? isq0 : isq1) && kcol < NUM_P) {
                    const float* mr = (j < 2) ? mrow0 : mrow1;
                    if (!(mr[kcol] > 0.5f)) v = -1e9f;
                }
                sc[nt][j] = v;
                if (j < 2) nm0 = fmaxf(nm0, v);
                else nm1 = fmaxf(nm1, v);
            }
        }
        nm0 = fmaxf(nm0, __shfl_xor_sync(0xffffffffu, nm0, 1));
        nm0 = fmaxf(nm0, __shfl_xor_sync(0xffffffffu, nm0, 2));
        nm1 = fmaxf(nm1, __shfl_xor_sync(0xffffffffu, nm1, 1));
        nm1 = fmaxf(nm1, __shfl_xor_sync(0xffffffffu, nm1, 2));
        float alpha0 = __expf(m0 - nm0);
        float alpha1 = __expf(m1 - nm1);
        m0 = nm0; m1 = nm1;
        float ls0 = 0.f, ls1 = 0.f;
#pragma unroll
        for (int nt = 0; nt < 8; nt++) {
            float p0 = __expf(sc[nt][0] - m0);
            float p1 = __expf(sc[nt][1] - m0);
            float p2 = __expf(sc[nt][2] - m1);
            float p3 = __expf(sc[nt][3] - m1);
            sc[nt][0] = p0; sc[nt][1] = p1; sc[nt][2] = p2; sc[nt][3] = p3;
            ls0 += p0 + p1;
            ls1 += p2 + p3;
        }
        ls0 += __shfl_xor_sync(0xffffffffu, ls0, 1);
        ls0 += __shfl_xor_sync(0xffffffffu, ls0, 2);
        ls1 += __shfl_xor_sync(0xffffffffu, ls1, 1);
        ls1 += __shfl_xor_sync(0xffffffffu, ls1, 2);
        l0s = l0s * alpha0 + ls0;
        l1s = l1s * alpha1 + ls1;
#pragma unroll
        for (int nt = 0; nt < 8; nt++) {
            O[nt][0] *= alpha0; O[nt][1] *= alpha0;
            O[nt][2] *= alpha1; O[nt][3] *= alpha1;
        }

        // O += P V (3-term); P fragments built from sc in registers
#pragma unroll
        for (int kk = 0; kk < 4; kk++) {
            int t0 = kk * 2, t1 = kk * 2 + 1;
            uint32_t pah[4], pal[4];
            split_pack2(sc[t0][0], sc[t0][1], pah[0], pal[0]);
            split_pack2(sc[t0][2], sc[t0][3], pah[1], pal[1]);
            split_pack2(sc[t1][0], sc[t1][1], pah[2], pal[2]);
            split_pack2(sc[t1][2], sc[t1][3], pah[3], pal[3]);
#pragma unroll
            for (int bj = 0; bj < 4; bj++) {
                uint32_t voff = (uint32_t)((bj * 16 + laneRB) * AT_PITCH + kk * 16 + laneKB) * 2;
                uint32_t vh[4], vl[4];
                ldsm4(vh, sb + AOVH + voff);
                ldsm4(vl, sb + AOVL + voff);
                mma_bf16(O[bj * 2], pah, vh);
                mma_bf16(O[bj * 2], pah, vl);
                mma_bf16(O[bj * 2], pal, vh);
                mma_bf16(O[bj * 2 + 1], pah, vh + 2);
                mma_bf16(O[bj * 2 + 1], pah, vl + 2);
                mma_bf16(O[bj * 2 + 1], pal, vh + 2);
            }
        }
    }

    // write output (bf16 pair) with 1/l normalization
    float inv0 = 1.f / l0s, inv1 = 1.f / l1s;
    if (r0g < SEQ) {
        size_t base0 = (size_t)(b * SEQ + r0g) * EMB + h * 64;
#pragma unroll
        for (int nt = 0; nt < 8; nt++) {
            int cc = nt * 8 + tq * 2;
            float v0 = O[nt][0] * inv0, v1 = O[nt][1] * inv0;
            __nv_bfloat16 h0, lo0, h1, lo1;
            split_bf16(v0, h0, lo0);
            split_bf16(v1, h1, lo1);
            *(__nv_bfloat162*)(oh + base0 + cc) = __nv_bfloat162(h0, h1);
            *(__nv_bfloat162*)(ol + base0 + cc) = __nv_bfloat162(lo0, lo1);
        }
    }
    if (r1g < SEQ) {
        size_t base1 = (size_t)(b * SEQ + r1g) * EMB + h * 64;
#pragma unroll
        for (int nt = 0; nt < 8; nt++) {
            int cc = nt * 8 + tq * 2;
            float v0 = O[nt][2] * inv1, v1 = O[nt][3] * inv1;
            __nv_bfloat16 h0, lo0, h1, lo1;
            split_bf16(v0, h0, lo0);
            split_bf16(v1, h1, lo1);
            *(__nv_bfloat162*)(oh + base1 + cc) = __nv_bfloat162(h0, h1);
            *(__nv_bfloat162*)(ol + base1 + cc) = __nv_bfloat162(lo0, lo1);
        }
    }
}

// ---------------- launch ----------------
extern "C" void kernel_launch(void* const* d_in, const int* in_sizes, int n_in,
                              void* d_out, int out_size) {
    const float* x      = (const float*)d_in[0];
    const float* mask   = (const float*)d_in[1];
    const float* qkv_w  = (const float*)d_in[2];
    const float* proj_w = (const float*)d_in[3];
    const float* proj_b = (const float*)d_in[4];
    const float* ln1_g  = (const float*)d_in[5];
    const float* ln1_b  = (const float*)d_in[6];
    const float* ln2_g  = (const float*)d_in[7];
    const float* ln2_b  = (const float*)d_in[8];
    const float* fc1_w  = (const float*)d_in[9];
    const float* fc1_b  = (const float*)d_in[10];
    const float* fc2_w  = (const float*)d_in[11];
    const float* fc2_b  = (const float*)d_in[12];
    float* out = (float*)d_out;

    void *pqkv, *px1, *pxnh, *pxnl, *path, *patl, *phh, *phl;
    void *pwqh, *pwql, *pwph, *pwpl, *pw1h, *pw1l, *pw2h, *pw2l;
    cudaGetSymbolAddress(&pqkv, g_qkv);
    cudaGetSymbolAddress(&px1, g_x1);
    cudaGetSymbolAddress(&pxnh, g_xnh);
    cudaGetSymbolAddress(&pxnl, g_xnl);
    cudaGetSymbolAddress(&path, g_ath);
    cudaGetSymbolAddress(&patl, g_atl);
    cudaGetSymbolAddress(&phh, g_hh);
    cudaGetSymbolAddress(&phl, g_hl);
    cudaGetSymbolAddress(&pwqh, g_wqh);
    cudaGetSymbolAddress(&pwql, g_wql);
    cudaGetSymbolAddress(&pwph, g_wph);
    cudaGetSymbolAddress(&pwpl, g_wpl);
    cudaGetSymbolAddress(&pw1h, g_w1h);
    cudaGetSymbolAddress(&pw1l, g_w1l);
    cudaGetSymbolAddress(&pw2h, g_w2h);
    cudaGetSymbolAddress(&pw2l, g_w2l);
    float* qkv = (float*)pqkv;
    float* x1 = (float*)px1;
    __nv_bfloat16 *xnh = (__nv_bfloat16*)pxnh, *xnl = (__nv_bfloat16*)pxnl;
    __nv_bfloat16 *ath = (__nv_bfloat16*)path, *atl = (__nv_bfloat16*)patl;
    __nv_bfloat16 *hh = (__nv_bfloat16*)phh, *hl = (__nv_bfloat16*)phl;
    __nv_bfloat16 *wqh = (__nv_bfloat16*)pwqh, *wql = (__nv_bfloat16*)pwql;
    __nv_bfloat16 *wph = (__nv_bfloat16*)pwph, *wpl = (__nv_bfloat16*)pwpl;
    __nv_bfloat16 *w1h = (__nv_bfloat16*)pw1h, *w1l = (__nv_bfloat16*)pw1l;
    __nv_bfloat16 *w2h = (__nv_bfloat16*)pw2h, *w2l = (__nv_bfloat16*)pw2l;

    cudaFuncSetAttribute(gemm2_kernel, cudaFuncAttributeMaxDynamicSharedMemorySize, GEMM_SMEM);
    cudaFuncSetAttribute(attn_mma_kernel, cudaFuncAttributeMaxDynamicSharedMemorySize, ATTN_SMEM);

    const int MG = (M_ROWS + GBM - 1) / GBM;  // 71
    dim3 tb(32, 8);

    // 0) weight convert + transpose
    wconv_kernel<<<dim3(3 * EMB / 32, EMB / 32), tb>>>(qkv_w, wqh, wql, EMB, 3 * EMB);
    wconv_kernel<<<dim3(EMB / 32, EMB / 32), tb>>>(proj_w, wph, wpl, EMB, EMB);
    wconv_kernel<<<dim3(MLP / 32, EMB / 32), tb>>>(fc1_w, w1h, w1l, EMB, MLP);
    wconv_kernel<<<dim3(EMB / 32, MLP / 32), tb>>>(fc2_w, w2h, w2l, MLP, EMB);

    // 1) LN1 -> bf16 pairs
    ln_kernel<<<M_ROWS, 256>>>(x, ln1_g, ln1_b, xnh, xnl);
    // 2) QKV GEMM -> fp32 qkv
    gemm2_kernel<<<dim3(3 * EMB / GBN, MG), 256, GEMM_SMEM>>>(
        xnh, xnl, wqh, wql, qkv, nullptr, nullptr, M_ROWS, 3 * EMB, EMB,
        nullptr, nullptr, 0);
    // 3) attention (tensor-core flash) -> bf16 pairs
    attn_mma_kernel<<<dim3((SEQ + AT_QT - 1) / AT_QT, NH, B_), 256, ATTN_SMEM>>>(
        qkv, mask, ath, atl);
    // 4) proj + bias + residual(x) -> fp32 x1
    gemm2_kernel<<<dim3(EMB / GBN, MG), 256, GEMM_SMEM>>>(
        ath, atl, wph, wpl, x1, nullptr, nullptr, M_ROWS, EMB, EMB,
        proj_b, x, 0);
    // 5) LN2 -> bf16 pairs
    ln_kernel<<<M_ROWS, 256>>>(x1, ln2_g, ln2_b, xnh, xnl);
    // 6) fc1 + bias + gelu -> bf16 pairs
    gemm2_kernel<<<dim3(MLP / GBN, MG), 256, GEMM_SMEM>>>(
        xnh, xnl, w1h, w1l, nullptr, hh, hl, M_ROWS, MLP, EMB,
        fc1_b, nullptr, 1);
    // 7) fc2 + bias + residual(x1) -> out
    gemm2_kernel<<<dim3(EMB / GBN, MG), 256, GEMM_SMEM>>>(
        hh, hl, w2h, w2l, out, nullptr, nullptr, M_ROWS, EMB, MLP,
        fc2_b, x1, 0);
}

// round 10
// speedup vs baseline: 3.0457x; 1.0025x over previous
#include <cuda_runtime.h>
#include <cuda_bf16.h>
#include <math.h>
#include <stdint.h>

#define B_ 8
#define SEQ 1124
#define EMB 1024
#define NH 16
#define HD 64
#define MLP 4096
#define M_ROWS (B_ * SEQ)          // 8992
#define NUM_Q 100
#define NUM_P 1024

// ---------------- scratch (device globals; no allocation allowed) ----------------
__device__ float g_qkv[(size_t)M_ROWS * 3 * EMB];
__device__ float g_x1[(size_t)M_ROWS * EMB];
// activation bf16 hi/lo pairs
__device__ __nv_bfloat16 g_xnh[(size_t)M_ROWS * EMB];
__device__ __nv_bfloat16 g_xnl[(size_t)M_ROWS * EMB];
__device__ __nv_bfloat16 g_ath[(size_t)M_ROWS * EMB];
__device__ __nv_bfloat16 g_atl[(size_t)M_ROWS * EMB];
__device__ __nv_bfloat16 g_hh[(size_t)M_ROWS * MLP];
__device__ __nv_bfloat16 g_hl[(size_t)M_ROWS * MLP];
// transposed weight bf16 hi/lo pairs ([N][K] layout)
__device__ __nv_bfloat16 g_wqh[(size_t)3 * EMB * EMB];
__device__ __nv_bfloat16 g_wql[(size_t)3 * EMB * EMB];
__device__ __nv_bfloat16 g_wph[(size_t)EMB * EMB];
__device__ __nv_bfloat16 g_wpl[(size_t)EMB * EMB];
__device__ __nv_bfloat16 g_w1h[(size_t)MLP * EMB];
__device__ __nv_bfloat16 g_w1l[(size_t)MLP * EMB];
__device__ __nv_bfloat16 g_w2h[(size_t)EMB * MLP];
__device__ __nv_bfloat16 g_w2l[(size_t)EMB * MLP];

// ---------------- helpers ----------------
__device__ __forceinline__ uint32_t smem_u32(const void* p) {
    uint32_t a;
    asm("{ .reg .u64 t; cvta.to.shared.u64 t, %1; cvt.u32.u64 %0, t; }" : "=r"(a) : "l"(p));
    return a;
}
__device__ __forceinline__ void cp16(uint32_t dst, const void* src) {
    asm volatile("cp.async.cg.shared.global [%0], [%1], 16;" :: "r"(dst), "l"(src) : "memory");
}
__device__ __forceinline__ void cp_commit() { asm volatile("cp.async.commit_group;" ::: "memory"); }
template <int NN>
__device__ __forceinline__ void cp_wait() { asm volatile("cp.async.wait_group %0;" :: "n"(NN) : "memory"); }
__device__ __forceinline__ void ldsm4(uint32_t* r, uint32_t addr) {
    asm volatile("ldmatrix.sync.aligned.m8n8.x4.shared.b16 {%0,%1,%2,%3}, [%4];"
        : "=r"(r[0]), "=r"(r[1]), "=r"(r[2]), "=r"(r[3]) : "r"(addr));
}
__device__ __forceinline__ void mma_bf16(float* d, const uint32_t* a, const uint32_t* b) {
    asm volatile("mma.sync.aligned.m16n8k16.row.col.f32.bf16.bf16.f32 "
        "{%0,%1,%2,%3}, {%4,%5,%6,%7}, {%8,%9}, {%0,%1,%2,%3};"
        : "+f"(d[0]), "+f"(d[1]), "+f"(d[2]), "+f"(d[3])
        : "r"(a[0]), "r"(a[1]), "r"(a[2]), "r"(a[3]), "r"(b[0]), "r"(b[1]));
}
__device__ __forceinline__ void split_bf16(float x, __nv_bfloat16& h, __nv_bfloat16& l) {
    h = __float2bfloat16_rn(x);
    l = __float2bfloat16_rn(x - __bfloat162float(h));
}
__device__ __forceinline__ void split_pack2(float x, float y, uint32_t& ph, uint32_t& pl) {
    __nv_bfloat16 hx, lx, hy, ly;
    split_bf16(x, hx, lx);
    split_bf16(y, hy, ly);
    __nv_bfloat162 H(hx, hy), L(lx, ly);
    ph = *(uint32_t*)&H;
    pl = *(uint32_t*)&L;
}

// ---------------- weight convert + transpose: W[K][N] fp32 -> Th/Tl[N][K] bf16 ----------------
__global__ void __launch_bounds__(256) wconv_kernel(const float* __restrict__ W,
                                                    __nv_bfloat16* __restrict__ Th,
                                                    __nv_bfloat16* __restrict__ Tl,
                                                    int K, int N) {
    __shared__ float ts[32][33];
    int n0 = blockIdx.x * 32, k0 = blockIdx.y * 32;
    int tx = threadIdx.x, ty = threadIdx.y;
#pragma unroll
    for (int i = 0; i < 4; i++)
        ts[ty + 8 * i][tx] = W[(size_t)(k0 + ty + 8 * i) * N + n0 + tx];
    __syncthreads();
#pragma unroll
    for (int i = 0; i < 4; i++) {
        float v = ts[tx][ty + 8 * i];
        __nv_bfloat16 h, l;
        split_bf16(v, h, l);
        size_t o = (size_t)(n0 + ty + 8 * i) * K + k0 + tx;
        Th[o] = h; Tl[o] = l;
    }
}

// ---------------- LayerNorm -> bf16 hi/lo pairs ----------------
__global__ void __launch_bounds__(256) ln_kernel(const float* __restrict__ x,
                                                 const float* __restrict__ g,
                                                 const float* __restrict__ b,
                                                 __nv_bfloat16* __restrict__ oh,
                                                 __nv_bfloat16* __restrict__ ol) {
    int row = blockIdx.x;
    const float* xr = x + (size_t)row * EMB;
    int t = threadIdx.x;
    float v[4];
    float s = 0.f, s2 = 0.f;
#pragma unroll
    for (int i = 0; i < 4; i++) {
        float val = xr[t + i * 256];
        v[i] = val;
        s += val;
        s2 += val * val;
    }
#pragma unroll
    for (int o = 16; o > 0; o >>= 1) {
        s += __shfl_xor_sync(0xffffffffu, s, o);
        s2 += __shfl_xor_sync(0xffffffffu, s2, o);
    }
    __shared__ float red[2][8];
    int w = t >> 5, lane = t & 31;
    if (lane == 0) { red[0][w] = s; red[1][w] = s2; }
    __syncthreads();
    float ts = 0.f, ts2 = 0.f;
#pragma unroll
    for (int i = 0; i < 8; i++) { ts += red[0][i]; ts2 += red[1][i]; }
    float mean = ts * (1.0f / EMB);
    float var = ts2 * (1.0f / EMB) - mean * mean;
    float inv = rsqrtf(var + 1e-6f);
#pragma unroll
    for (int i = 0; i < 4; i++) {
        int c = t + i * 256;
        float y = (v[i] - mean) * inv * g[c] + b[c];
        __nv_bfloat16 h, l;
        split_bf16(y, h, l);
        oh[(size_t)row * EMB + c] = h;
        ol[(size_t)row * EMB + c] = l;
    }
}

// ---------------- bf16 pair GEMM, cp.async 2-stage pipeline, tile 128x128x64 ----------------
#define GBM 128
#define GBN 128
#define GBK 64
#define PITCH 72                       // bf16 elems per smem row (144B)
#define ARR_BYTES (128 * PITCH * 2)    // 18432
#define OFA_H 0
#define OFA_L (ARR_BYTES)
#define OFB_H (2 * ARR_BYTES)
#define OFB_L (3 * ARR_BYTES)
#define STAGE_BYTES (4 * ARR_BYTES)    // 73728
#define GEMM_SMEM (2 * STAGE_BYTES)    // 147456

__global__ void __launch_bounds__(256) gemm2_kernel(const __nv_bfloat16* __restrict__ Ah,
                                                    const __nv_bfloat16* __restrict__ Al,
                                                    const __nv_bfloat16* __restrict__ Bh,
                                                    const __nv_bfloat16* __restrict__ Bl,
                                                    float* __restrict__ C,
                                                    __nv_bfloat16* __restrict__ Ch,
                                                    __nv_bfloat16* __restrict__ Cl,
                                                    int M, int N, int K,
                                                    const float* __restrict__ bias,
                                                    const float* __restrict__ resid,
                                                    int do_gelu) {
    extern __shared__ char dsm[];
    uint32_t sb = smem_u32(dsm);
    int tid = threadIdx.x;
    int lane = tid & 31, wid = tid >> 5;
    int warp_m = wid >> 2;
    int warp_n = wid & 3;
    int row0 = blockIdx.y * GBM;
    int col0 = blockIdx.x * GBN;

    int laneRA = (lane & 7) + ((lane >> 3) & 1) * 8;
    int laneKA = ((lane >> 4) & 1) * 8;
    int laneRB = (lane & 7) + ((lane >> 4) & 1) * 8;
    int laneKB = ((lane >> 3) & 1) * 8;

    float acc[4][4][4];
#pragma unroll
    for (int i = 0; i < 4; i++)
#pragma unroll
        for (int j = 0; j < 4; j++)
#pragma unroll
            for (int r = 0; r < 4; r++) acc[i][j][r] = 0.f;

    auto load_stage = [&](int buf, int k0) {
        uint32_t base = sb + buf * STAGE_BYTES;
#pragma unroll
        for (int t = 0; t < 4; t++) {
            int c = tid + t * 256;
            int row = c >> 3;
            int col = c & 7;
            uint32_t doff = (uint32_t)(row * 144 + col * 16);
            int gm = row0 + row; if (gm >= M) gm = M - 1;
            size_t aoff = (size_t)gm * K + k0 + col * 8;
            cp16(base + OFA_H + doff, Ah + aoff);
            cp16(base + OFA_L + doff, Al + aoff);
            int gn = col0 + row;
            size_t boff = (size_t)gn * K + k0 + col * 8;
            cp16(base + OFB_H + doff, Bh + boff);
            cp16(base + OFB_L + doff, Bl + boff);
        }
        cp_commit();
    };

    int nstages = K / GBK;
    load_stage(0, 0);

    for (int s = 0; s < nstages; s++) {
        int buf = s & 1;
        if (s + 1 < nstages) {
            load_stage(buf ^ 1, (s + 1) * GBK);
            cp_wait<1>();
        } else {
            cp_wait<0>();
        }
        __syncthreads();

        uint32_t base = sb + buf * STAGE_BYTES;
#pragma unroll
        for (int ks = 0; ks < 4; ks++) {
            int kb = ks * 16;
            uint32_t ah[16], al[16], bh[8], bl[8];
#pragma unroll
            for (int mi = 0; mi < 4; mi++) {
                int mr = warp_m * 64 + mi * 16 + laneRA;
                uint32_t off = (uint32_t)(mr * PITCH + kb + laneKA) * 2;
                ldsm4(ah + mi * 4, base + OFA_H + off);
                ldsm4(al + mi * 4, base + OFA_L + off);
            }
#pragma unroll
            for (int bj = 0; bj < 2; bj++) {
                int nr = warp_n * 32 + bj * 16 + laneRB;
                uint32_t off = (uint32_t)(nr * PITCH + kb + laneKB) * 2;
                ldsm4(bh + bj * 4, base + OFB_H + off);
                ldsm4(bl + bj * 4, base + OFB_L + off);
            }
#pragma unroll
            for (int mi = 0; mi < 4; mi++)
#pragma unroll
                for (int nj = 0; nj < 4; nj++) {
                    mma_bf16(acc[mi][nj], ah + mi * 4, bh + nj * 2);
                    mma_bf16(acc[mi][nj], ah + mi * 4, bl + nj * 2);
                    mma_bf16(acc[mi][nj], al + mi * 4, bh + nj * 2);
                }
        }
        __syncthreads();
    }

    int quad = lane >> 2, tq = lane & 3;
#pragma unroll
    for (int mi = 0; mi < 4; mi++) {
#pragma unroll
        for (int half = 0; half < 2; half++) {
            int gr = row0 + warp_m * 64 + mi * 16 + quad + half * 8;
            if (gr >= M) continue;
#pragma unroll
            for (int nj = 0; nj < 4; nj++) {
                int gc = col0 + warp_n * 32 + nj * 8 + tq * 2;
                float v0 = acc[mi][nj][half * 2 + 0];
                float v1 = acc[mi][nj][half * 2 + 1];
                if (bias) { v0 += bias[gc]; v1 += bias[gc + 1]; }
                if (do_gelu) {
                    v0 = 0.5f * v0 * (1.0f + erff(v0 * 0.70710678118f));
                    v1 = 0.5f * v1 * (1.0f + erff(v1 * 0.70710678118f));
                }
                if (resid) {
                    const float* rp = resid + (size_t)gr * N + gc;
                    v0 += rp[0]; v1 += rp[1];
                }
                if (Ch) {
                    __nv_bfloat16 h0, l0, h1, l1;
                    split_bf16(v0, h0, l0);
                    split_bf16(v1, h1, l1);
                    *(__nv_bfloat162*)(Ch + (size_t)gr * N + gc) = __nv_bfloat162(h0, h1);
                    *(__nv_bfloat162*)(Cl + (size_t)gr * N + gc) = __nv_bfloat162(l0, l1);
                } else {
                    *(float2*)(C + (size_t)gr * N + gc) = make_float2(v0, v1);
                }
            }
        }
    }
}

// ---------------- mma-based flash attention ----------------
// 128 q-rows per CTA (8 warps x 16 rows), K chunks of 64.
// Q,K hi/lo split in smem; V stored transposed [hd][kpos] hi/lo.
#define AT_QT 128
#define AT_KC 64
#define AT_PITCH 72
#define AT_NCH ((SEQ + AT_KC - 1) / AT_KC)          // 18
#define AOQH 0
#define AOQL (AOQH + AT_QT * AT_PITCH * 2)          // 18432
#define AOKH (AOQL + AT_QT * AT_PITCH * 2)          // 36864
#define AOKL (AOKH + AT_KC * AT_PITCH * 2)          // 46080
#define AOVH (AOKL + AT_KC * AT_PITCH * 2)          // 55296
#define AOVL (AOVH + AT_KC * AT_PITCH * 2)          // 64512
#define ATTN_SMEM (AOVL + AT_KC * AT_PITCH * 2)     // 73728

__global__ void __launch_bounds__(256) attn_mma_kernel(const float* __restrict__ qkv,
                                                       const float* __restrict__ mask,
                                                       __nv_bfloat16* __restrict__ oh,
                                                       __nv_bfloat16* __restrict__ ol) {
    extern __shared__ char dsm[];
    uint32_t sb = smem_u32(dsm);
    __nv_bfloat16* sQh = (__nv_bfloat16*)(dsm + AOQH);
    __nv_bfloat16* sQl = (__nv_bfloat16*)(dsm + AOQL);
    __nv_bfloat16* sKh = (__nv_bfloat16*)(dsm + AOKH);
    __nv_bfloat16* sKl = (__nv_bfloat16*)(dsm + AOKL);
    __nv_bfloat16* sVh = (__nv_bfloat16*)(dsm + AOVH);
    __nv_bfloat16* sVl = (__nv_bfloat16*)(dsm + AOVL);

    int qt = blockIdx.x, h = blockIdx.y, b = blockIdx.z;
    int q0 = qt * AT_QT;
    int tid = threadIdx.x;
    int lane = tid & 31, wid = tid >> 5;
    int quad = lane >> 2, tq = lane & 3;

    int laneRA = (lane & 7) + ((lane >> 3) & 1) * 8;
    int laneKA = ((lane >> 4) & 1) * 8;
    int laneRB = (lane & 7) + ((lane >> 4) & 1) * 8;
    int laneKB = ((lane >> 3) & 1) * 8;

    // load Q (scaled by 1/8, exact), split hi/lo
#pragma unroll
    for (int l = 0; l < 8; l++) {
        int e = tid + l * 256;
        int row = e >> 4;
        int c4 = (e & 15) * 4;
        int s = q0 + row;
        float4 qv = make_float4(0.f, 0.f, 0.f, 0.f);
        if (s < SEQ)
            qv = *(const float4*)(qkv + (size_t)(b * SEQ + s) * 3072 + h * 64 + c4);
        float xs[4] = {qv.x * 0.125f, qv.y * 0.125f, qv.z * 0.125f, qv.w * 0.125f};
#pragma unroll
        for (int u = 0; u < 4; u += 2) {
            __nv_bfloat16 h0, l0, h1, l1;
            split_bf16(xs[u], h0, l0);
            split_bf16(xs[u + 1], h1, l1);
            *(__nv_bfloat162*)&sQh[row * AT_PITCH + c4 + u] = __nv_bfloat162(h0, h1);
            *(__nv_bfloat162*)&sQl[row * AT_PITCH + c4 + u] = __nv_bfloat162(l0, l1);
        }
    }

    int mr0 = wid * 16;
    int r0g = q0 + mr0 + quad;
    int r1g = r0g + 8;
    bool isq0 = (r0g >= NUM_P) && (r0g < SEQ);
    bool isq1 = (r1g >= NUM_P) && (r1g < SEQ);
    const float* mrow0 = mask + ((size_t)b * NUM_Q + (isq0 ? r0g - NUM_P : 0)) * NUM_P;
    const float* mrow1 = mask + ((size_t)b * NUM_Q + (isq1 ? r1g - NUM_P : 0)) * NUM_P;

    float O[8][4];
#pragma unroll
    for (int i = 0; i < 8; i++)
#pragma unroll
        for (int j = 0; j < 4; j++) O[i][j] = 0.f;
    float m0 = -1e30f, m1 = -1e30f, l0s = 0.f, l1s = 0.f;

    for (int chunk = 0; chunk < AT_NCH; chunk++) {
        int c0 = chunk * AT_KC;
        __syncthreads();
        // load K chunk [kpos][d] and V chunk transposed [d][kpos]
#pragma unroll
        for (int l = 0; l < 4; l++) {
            int e = tid + l * 256;
            int kpos = e >> 4;
            int c4 = (e & 15) * 4;
            int s = c0 + kpos;
            float4 kv = make_float4(0.f, 0.f, 0.f, 0.f);
            float4 vv = make_float4(0.f, 0.f, 0.f, 0.f);
            if (s < SEQ) {
                const float* base = qkv + (size_t)(b * SEQ + s) * 3072 + h * 64 + c4;
                kv = *(const float4*)(base + 1024);
                vv = *(const float4*)(base + 2048);
            }
            float ks[4] = {kv.x, kv.y, kv.z, kv.w};
            float vs[4] = {vv.x, vv.y, vv.z, vv.w};
#pragma unroll
            for (int u = 0; u < 4; u += 2) {
                __nv_bfloat16 h0, lo0, h1, lo1;
                split_bf16(ks[u], h0, lo0);
                split_bf16(ks[u + 1], h1, lo1);
                *(__nv_bfloat162*)&sKh[kpos * AT_PITCH + c4 + u] = __nv_bfloat162(h0, h1);
                *(__nv_bfloat162*)&sKl[kpos * AT_PITCH + c4 + u] = __nv_bfloat162(lo0, lo1);
            }
#pragma unroll
            for (int u = 0; u < 4; u++) {
                __nv_bfloat16 hv, lv;
                split_bf16(vs[u], hv, lv);
                sVh[(c4 + u) * AT_PITCH + kpos] = hv;
                sVl[(c4 + u) * AT_PITCH + kpos] = lv;
            }
        }
        __syncthreads();

        // S = Q K^T (3-term)
        float sc[8][4];
#pragma unroll
        for (int i = 0; i < 8; i++)
#pragma unroll
            for (int j = 0; j < 4; j++) sc[i][j] = 0.f;
#pragma unroll
        for (int ks = 0; ks < 4; ks++) {
            int kb = ks * 16;
            uint32_t ah[4], al[4];
            uint32_t aoff = (uint32_t)((mr0 + laneRA) * AT_PITCH + kb + laneKA) * 2;
            ldsm4(ah, sb + AOQH + aoff);
            ldsm4(al, sb + AOQL + aoff);
#pragma unroll
            for (int bj = 0; bj < 4; bj++) {
                uint32_t boff = (uint32_t)((bj * 16 + laneRB) * AT_PITCH + kb + laneKB) * 2;
                uint32_t bh[4], bl[4];
                ldsm4(bh, sb + AOKH + boff);
                ldsm4(bl, sb + AOKL + boff);
                mma_bf16(sc[bj * 2], ah, bh);
                mma_bf16(sc[bj * 2], ah, bl);
                mma_bf16(sc[bj * 2], al, bh);
                mma_bf16(sc[bj * 2 + 1], ah, bh + 2);
                mma_bf16(sc[bj * 2 + 1], ah, bl + 2);
                mma_bf16(sc[bj * 2 + 1], al, bh + 2);
            }
        }

        // mask + online softmax
        float nm0 = m0, nm1 = m1;
#pragma unroll
        for (int nt = 0; nt < 8; nt++) {
#pragma unroll
            for (int j = 0; j < 4; j++) {
                int kcol = c0 + nt * 8 + tq * 2 + (j & 1);
                float v = sc[nt][j];
                if (kcol >= SEQ) {
                    v = -1e30f;
                } else if ((j < 2 ? isq0 : isq1) && kcol < NUM_P) {
                    const float* mr = (j < 2) ? mrow0 : mrow1;
                    if (!(mr[kcol] > 0.5f)) v = -1e9f;
                }
                sc[nt][j] = v;
                if (j < 2) nm0 = fmaxf(nm0, v);
                else nm1 = fmaxf(nm1, v);
            }
        }
        nm0 = fmaxf(nm0, __shfl_xor_sync(0xffffffffu, nm0, 1));
        nm0 = fmaxf(nm0, __shfl_xor_sync(0xffffffffu, nm0, 2));
        nm1 = fmaxf(nm1, __shfl_xor_sync(0xffffffffu, nm1, 1));
        nm1 = fmaxf(nm1, __shfl_xor_sync(0xffffffffu, nm1, 2));
        float alpha0 = __expf(m0 - nm0);
        float alpha1 = __expf(m1 - nm1);
        m0 = nm0; m1 = nm1;
        float ls0 = 0.f, ls1 = 0.f;
#pragma unroll
        for (int nt = 0; nt < 8; nt++) {
            float p0 = __expf(sc[nt][0] - m0);
            float p1 = __expf(sc[nt][1] - m0);
            float p2 = __expf(sc[nt][2] - m1);
            float p3 = __expf(sc[nt][3] - m1);
            sc[nt][0] = p0; sc[nt][1] = p1; sc[nt][2] = p2; sc[nt][3] = p3;
            ls0 += p0 + p1;
            ls1 += p2 + p3;
        }
        ls0 += __shfl_xor_sync(0xffffffffu, ls0, 1);
        ls0 += __shfl_xor_sync(0xffffffffu, ls0, 2);
        ls1 += __shfl_xor_sync(0xffffffffu, ls1, 1);
        ls1 += __shfl_xor_sync(0xffffffffu, ls1, 2);
        l0s = l0s * alpha0 + ls0;
        l1s = l1s * alpha1 + ls1;
#pragma unroll
        for (int nt = 0; nt < 8; nt++) {
            O[nt][0] *= alpha0; O[nt][1] *= alpha0;
            O[nt][2] *= alpha1; O[nt][3] *= alpha1;
        }

        // O += P V (3-term); P fragments built from sc in registers
#pragma unroll
        for (int kk = 0; kk < 4; kk++) {
            int t0 = kk * 2, t1 = kk * 2 + 1;
            uint32_t pah[4], pal[4];
            split_pack2(sc[t0][0], sc[t0][1], pah[0], pal[0]);
            split_pack2(sc[t0][2], sc[t0][3], pah[1], pal[1]);
            split_pack2(sc[t1][0], sc[t1][1], pah[2], pal[2]);
            split_pack2(sc[t1][2], sc[t1][3], pah[3], pal[3]);
#pragma unroll
            for (int bj = 0; bj < 4; bj++) {
                uint32_t voff = (uint32_t)((bj * 16 + laneRB) * AT_PITCH + kk * 16 + laneKB) * 2;
                uint32_t vh[4], vl[4];
                ldsm4(vh, sb + AOVH + voff);
                ldsm4(vl, sb + AOVL + voff);
                mma_bf16(O[bj * 2], pah, vh);
                mma_bf16(O[bj * 2], pah, vl);
                mma_bf16(O[bj * 2], pal, vh);
                mma_bf16(O[bj * 2 + 1], pah, vh + 2);
                mma_bf16(O[bj * 2 + 1], pah, vl + 2);
                mma_bf16(O[bj * 2 + 1], pal, vh + 2);
            }
        }
    }

    // write output (bf16 pair) with 1/l normalization
    float inv0 = 1.f / l0s, inv1 = 1.f / l1s;
    if (r0g < SEQ) {
        size_t base0 = (size_t)(b * SEQ + r0g) * EMB + h * 64;
#pragma unroll
        for (int nt = 0; nt < 8; nt++) {
            int cc = nt * 8 + tq * 2;
            float v0 = O[nt][0] * inv0, v1 = O[nt][1] * inv0;
            __nv_bfloat16 h0, lo0, h1, lo1;
            split_bf16(v0, h0, lo0);
            split_bf16(v1, h1, lo1);
            *(__nv_bfloat162*)(oh + base0 + cc) = __nv_bfloat162(h0, h1);
            *(__nv_bfloat162*)(ol + base0 + cc) = __nv_bfloat162(lo0, lo1);
        }
    }
    if (r1g < SEQ) {
        size_t base1 = (size_t)(b * SEQ + r1g) * EMB + h * 64;
#pragma unroll
        for (int nt = 0; nt < 8; nt++) {
            int cc = nt * 8 + tq * 2;
            float v0 = O[nt][2] * inv1, v1 = O[nt][3] * inv1;
            __nv_bfloat16 h0, lo0, h1, lo1;
            split_bf16(v0, h0, lo0);
            split_bf16(v1, h1, lo1);
            *(__nv_bfloat162*)(oh + base1 + cc) = __nv_bfloat162(h0, h1);
            *(__nv_bfloat162*)(ol + base1 + cc) = __nv_bfloat162(lo0, lo1);
        }
    }
}

// ---------------- launch ----------------
extern "C" void kernel_launch(void* const* d_in, const int* in_sizes, int n_in,
                              void* d_out, int out_size) {
    const float* x      = (const float*)d_in[0];
    const float* mask   = (const float*)d_in[1];
    const float* qkv_w  = (const float*)d_in[2];
    const float* proj_w = (const float*)d_in[3];
    const float* proj_b = (const float*)d_in[4];
    const float* ln1_g  = (const float*)d_in[5];
    const float* ln1_b  = (const float*)d_in[6];
    const float* ln2_g  = (const float*)d_in[7];
    const float* ln2_b  = (const float*)d_in[8];
    const float* fc1_w  = (const float*)d_in[9];
    const float* fc1_b  = (const float*)d_in[10];
    const float* fc2_w  = (const float*)d_in[11];
    const float* fc2_b  = (const float*)d_in[12];
    float* out = (float*)d_out;

    void *pqkv, *px1, *pxnh, *pxnl, *path, *patl, *phh, *phl;
    void *pwqh, *pwql, *pwph, *pwpl, *pw1h, *pw1l, *pw2h, *pw2l;
    cudaGetSymbolAddress(&pqkv, g_qkv);
    cudaGetSymbolAddress(&px1, g_x1);
    cudaGetSymbolAddress(&pxnh, g_xnh);
    cudaGetSymbolAddress(&pxnl, g_xnl);
    cudaGetSymbolAddress(&path, g_ath);
    cudaGetSymbolAddress(&patl, g_atl);
    cudaGetSymbolAddress(&phh, g_hh);
    cudaGetSymbolAddress(&phl, g_hl);
    cudaGetSymbolAddress(&pwqh, g_wqh);
    cudaGetSymbolAddress(&pwql, g_wql);
    cudaGetSymbolAddress(&pwph, g_wph);
    cudaGetSymbolAddress(&pwpl, g_wpl);
    cudaGetSymbolAddress(&pw1h, g_w1h);
    cudaGetSymbolAddress(&pw1l, g_w1l);
    cudaGetSymbolAddress(&pw2h, g_w2h);
    cudaGetSymbolAddress(&pw2l, g_w2l);
    float* qkv = (float*)pqkv;
    float* x1 = (float*)px1;
    __nv_bfloat16 *xnh = (__nv_bfloat16*)pxnh, *xnl = (__nv_bfloat16*)pxnl;
    __nv_bfloat16 *ath = (__nv_bfloat16*)path, *atl = (__nv_bfloat16*)patl;
    __nv_bfloat16 *hh = (__nv_bfloat16*)phh, *hl = (__nv_bfloat16*)phl;
    __nv_bfloat16 *wqh = (__nv_bfloat16*)pwqh, *wql = (__nv_bfloat16*)pwql;
    __nv_bfloat16 *wph = (__nv_bfloat16*)pwph, *wpl = (__nv_bfloat16*)pwpl;
    __nv_bfloat16 *w1h = (__nv_bfloat16*)pw1h, *w1l = (__nv_bfloat16*)pw1l;
    __nv_bfloat16 *w2h = (__nv_bfloat16*)pw2h, *w2l = (__nv_bfloat16*)pw2l;

    cudaFuncSetAttribute(gemm2_kernel, cudaFuncAttributeMaxDynamicSharedMemorySize, GEMM_SMEM);
    cudaFuncSetAttribute(attn_mma_kernel, cudaFuncAttributeMaxDynamicSharedMemorySize, ATTN_SMEM);

    const int MG = (M_ROWS + GBM - 1) / GBM;  // 71
    dim3 tb(32, 8);

    // 0) weight convert + transpose
    wconv_kernel<<<dim3(3 * EMB / 32, EMB / 32), tb>>>(qkv_w, wqh, wql, EMB, 3 * EMB);
    wconv_kernel<<<dim3(EMB / 32, EMB / 32), tb>>>(proj_w, wph, wpl, EMB, EMB);
    wconv_kernel<<<dim3(MLP / 32, EMB / 32), tb>>>(fc1_w, w1h, w1l, EMB, MLP);
    wconv_kernel<<<dim3(EMB / 32, MLP / 32), tb>>>(fc2_w, w2h, w2l, MLP, EMB);

    // 1) LN1 -> bf16 pairs
    ln_kernel<<<M_ROWS, 256>>>(x, ln1_g, ln1_b, xnh, xnl);
    // 2) QKV GEMM -> fp32 qkv
    gemm2_kernel<<<dim3(3 * EMB / GBN, MG), 256, GEMM_SMEM>>>(
        xnh, xnl, wqh, wql, qkv, nullptr, nullptr, M_ROWS, 3 * EMB, EMB,
        nullptr, nullptr, 0);
    // 3) attention (tensor-core flash) -> bf16 pairs
    attn_mma_kernel<<<dim3((SEQ + AT_QT - 1) / AT_QT, NH, B_), 256, ATTN_SMEM>>>(
        qkv, mask, ath, atl);
    // 4) proj + bias + residual(x) -> fp32 x1
    gemm2_kernel<<<dim3(EMB / GBN, MG), 256, GEMM_SMEM>>>(
        ath, atl, wph, wpl, x1, nullptr, nullptr, M_ROWS, EMB, EMB,
        proj_b, x, 0);
    // 5) LN2 -> bf16 pairs
    ln_kernel<<<M_ROWS, 256>>>(x1, ln2_g, ln2_b, xnh, xnl);
    // 6) fc1 + bias + gelu -> bf16 pairs
    gemm2_kernel<<<dim3(MLP / GBN, MG), 256, GEMM_SMEM>>>(
        xnh, xnl, w1h, w1l, nullptr, hh, hl, M_ROWS, MLP, EMB,
        fc1_b, nullptr, 1);
    // 7) fc2 + bias + residual(x1) -> out
    gemm2_kernel<<<dim3(EMB / GBN, MG), 256, GEMM_SMEM>>>(
        hh, hl, w2h, w2l, out, nullptr, nullptr, M_ROWS, EMB, MLP,
        fc2_b, x1, 0);
}